// round 4
// baseline (speedup 1.0000x reference)
#include <cuda_runtime.h>
#include <cuda_bf16.h>
#include <cstdint>

// ---------------------------------------------------------------------------
// GCN forward:  N=50000 nodes, E=800000 edges, F_IN=128, H=256, G=256, O=32, L=3
//
// NOTE: edge_index / batch are **int32** (JAX default config demotes int64).
//
// Pipeline per launch (all on default stream, graph-capturable, alloc-free):
//   1. degree histogram (+self loops) -> dis = rsqrt(deg)
//   2. CSR-by-destination build (counting sort), edge weight w = dis[s]*dis[d]
//   3. encoder GEMM  h = x @ enc_w + enc_b            (50000x128x256)
//   4. 3x { hw = h @ conv_w[l];  h = CSR-aggregate(hw) + conv_b[l] }
//   5. sorted-batch pooling -> hg = [sum | max | mean]  (256 x 768)
//   6. readout MLP -> out (256 x 32)
// ---------------------------------------------------------------------------

#define NN 50000
#define NE 800000
#define FIN 128
#define HD 256
#define NG 256
#define NO 32
#define NL 3
#define ETOT (NE + NN)

// ----------------------------- device scratch ------------------------------
__device__ float g_h[(size_t)NN * HD];     // 51.2 MB
__device__ float g_hw[(size_t)NN * HD];    // 51.2 MB
__device__ int   g_counts[NN];
__device__ int   g_cursor[NN];
__device__ float g_dis[NN];
__device__ int   g_offsets[NN + 1];
__device__ int   g_csr_src[ETOT];
__device__ float g_csr_w[ETOT];
__device__ int   g_gcount[NG];
__device__ int   g_gstart[NG + 1];
__device__ float g_hg[NG * 3 * HD];

// ------------------------------ setup kernels ------------------------------
__global__ void k_init() {
    int i = blockIdx.x * blockDim.x + threadIdx.x;
    if (i < NN) { g_counts[i] = 1; g_cursor[i] = 0; }   // count=1: self loop
    if (i < NG) g_gcount[i] = 0;
}

__global__ void k_count_deg(const int* __restrict__ ei) {
    int e = blockIdx.x * blockDim.x + threadIdx.x;
    if (e < NE) atomicAdd(&g_counts[ei[NE + e]], 1);  // dst row
}

__global__ void k_dis() {
    int i = blockIdx.x * blockDim.x + threadIdx.x;
    if (i < NN) g_dis[i] = rsqrtf((float)g_counts[i]);
}

// single-block inclusive scan over g_counts -> exclusive g_offsets (NN+1)
__global__ void k_scan_offsets() {
    __shared__ int sd[1024];
    __shared__ int running;
    int t = threadIdx.x;
    if (t == 0) { running = 0; g_offsets[0] = 0; }
    __syncthreads();
    for (int base = 0; base < NN; base += 1024) {
        int i = base + t;
        int v = (i < NN) ? g_counts[i] : 0;
        sd[t] = v;
        __syncthreads();
        #pragma unroll
        for (int off = 1; off < 1024; off <<= 1) {
            int tmp = (t >= off) ? sd[t - off] : 0;
            __syncthreads();
            if (t >= off) sd[t] += tmp;
            __syncthreads();
        }
        if (i < NN) g_offsets[i + 1] = running + sd[t];
        __syncthreads();
        if (t == 0) running += sd[1023];
        __syncthreads();
    }
}

__global__ void k_fill_self() {
    int i = blockIdx.x * blockDim.x + threadIdx.x;
    if (i < NN) {
        int pos = g_offsets[i] + atomicAdd(&g_cursor[i], 1);
        g_csr_src[pos] = i;
        float d = g_dis[i];
        g_csr_w[pos] = d * d;
    }
}

__global__ void k_fill_edges(const int* __restrict__ ei) {
    int e = blockIdx.x * blockDim.x + threadIdx.x;
    if (e < NE) {
        int s = ei[e];
        int d = ei[NE + e];
        int pos = g_offsets[d] + atomicAdd(&g_cursor[d], 1);
        g_csr_src[pos] = s;
        g_csr_w[pos] = g_dis[s] * g_dis[d];
    }
}

__global__ void k_batch_hist(const int* __restrict__ batch) {
    int i = blockIdx.x * blockDim.x + threadIdx.x;
    if (i < NN) atomicAdd(&g_gcount[batch[i]], 1);
}

__global__ void k_scan_graphs() {
    __shared__ int sd[NG];
    int t = threadIdx.x;
    sd[t] = g_gcount[t];
    __syncthreads();
    #pragma unroll
    for (int off = 1; off < NG; off <<= 1) {
        int tmp = (t >= off) ? sd[t - off] : 0;
        __syncthreads();
        if (t >= off) sd[t] += tmp;
        __syncthreads();
    }
    if (t == 0) g_gstart[0] = 0;
    g_gstart[t + 1] = sd[t];
}

// ------------------------------ SGEMM 128x128x8 ----------------------------
// C[M,N] = A[M,K] @ B[K,N] (+ bias[n]), row-major. 256 threads, 8x8 per thread.
__global__ void __launch_bounds__(256) k_sgemm(
    const float* __restrict__ A, const float* __restrict__ B,
    const float* __restrict__ bias, float* __restrict__ C,
    int M, int N, int K)
{
    __shared__ __align__(16) float As[8][128];
    __shared__ __align__(16) float Bs[8][128];
    int tid = threadIdx.x;
    int bm = blockIdx.x * 128;
    int bn = blockIdx.y * 128;

    int arow = tid >> 1;            // 0..127
    int ak   = (tid & 1) * 4;       // 0 or 4
    int brow = tid >> 5;            // 0..7
    int bcol = (tid & 31) * 4;      // 0..124

    int tx = tid & 15;              // col group
    int ty = tid >> 4;              // row group

    float acc[8][8];
    #pragma unroll
    for (int i = 0; i < 8; i++)
        #pragma unroll
        for (int j = 0; j < 8; j++) acc[i][j] = 0.f;

    for (int k0 = 0; k0 < K; k0 += 8) {
        float4 av = make_float4(0.f, 0.f, 0.f, 0.f);
        int gr = bm + arow;
        if (gr < M) av = *(const float4*)(A + (size_t)gr * K + k0 + ak);
        As[ak + 0][arow] = av.x;
        As[ak + 1][arow] = av.y;
        As[ak + 2][arow] = av.z;
        As[ak + 3][arow] = av.w;

        float4 bv = *(const float4*)(B + (size_t)(k0 + brow) * N + bn + bcol);
        *(float4*)&Bs[brow][bcol] = bv;
        __syncthreads();

        #pragma unroll
        for (int k = 0; k < 8; k++) {
            float a[8], b[8];
            *(float4*)&a[0] = *(const float4*)&As[k][ty * 8];
            *(float4*)&a[4] = *(const float4*)&As[k][ty * 8 + 4];
            *(float4*)&b[0] = *(const float4*)&Bs[k][tx * 8];
            *(float4*)&b[4] = *(const float4*)&Bs[k][tx * 8 + 4];
            #pragma unroll
            for (int i = 0; i < 8; i++)
                #pragma unroll
                for (int j = 0; j < 8; j++)
                    acc[i][j] = fmaf(a[i], b[j], acc[i][j]);
        }
        __syncthreads();
    }

    float bv[8];
    #pragma unroll
    for (int j = 0; j < 8; j++) bv[j] = bias ? bias[bn + tx * 8 + j] : 0.f;

    #pragma unroll
    for (int i = 0; i < 8; i++) {
        int gr = bm + ty * 8 + i;
        if (gr < M) {
            float4 o0, o1;
            o0.x = acc[i][0] + bv[0]; o0.y = acc[i][1] + bv[1];
            o0.z = acc[i][2] + bv[2]; o0.w = acc[i][3] + bv[3];
            o1.x = acc[i][4] + bv[4]; o1.y = acc[i][5] + bv[5];
            o1.z = acc[i][6] + bv[6]; o1.w = acc[i][7] + bv[7];
            float* cp = C + (size_t)gr * N + bn + tx * 8;
            *(float4*)cp       = o0;
            *(float4*)(cp + 4) = o1;
        }
    }
}

// ----------------------------- CSR aggregation -----------------------------
// h[i,f] = conv_b[f] + sum_{e in CSR row i} w[e] * hw[src[e], f]
__global__ void __launch_bounds__(HD) k_aggregate(const float* __restrict__ bias) {
    int i = blockIdx.x;
    int f = threadIdx.x;
    int beg = g_offsets[i];
    int end = g_offsets[i + 1];
    float acc = bias[f];
    for (int e = beg; e < end; ++e) {
        int s = g_csr_src[e];
        float w = g_csr_w[e];
        acc = fmaf(w, g_hw[(size_t)s * HD + f], acc);
    }
    g_h[(size_t)i * HD + f] = acc;
}

// -------------------------------- pooling ----------------------------------
__global__ void __launch_bounds__(HD) k_pool() {
    int g = blockIdx.x;
    int f = threadIdx.x;
    int beg = g_gstart[g], end = g_gstart[g + 1];
    float s = 0.f, m = -3.402823e38f;
    for (int i = beg; i < end; ++i) {
        float v = g_h[(size_t)i * HD + f];
        s += v;
        m = fmaxf(m, v);
    }
    int cnt = end - beg;
    g_hg[g * 3 * HD + f]            = s;
    g_hg[g * 3 * HD + HD + f]       = (cnt > 0) ? m : 0.f;
    g_hg[g * 3 * HD + 2 * HD + f]   = s / (float)(cnt > 0 ? cnt : 1);
}

// -------------------------------- readout ----------------------------------
__global__ void __launch_bounds__(128) k_readout(
    const float* __restrict__ r1w, const float* __restrict__ r1b,
    const float* __restrict__ r2w, const float* __restrict__ r2b,
    float* __restrict__ out)
{
    int g = blockIdx.x;
    int t = threadIdx.x;          // 128 threads
    __shared__ float sh[3 * HD];  // 768
    __shared__ float z[128];
    for (int i = t; i < 3 * HD; i += 128) sh[i] = g_hg[g * 3 * HD + i];
    __syncthreads();
    float acc = r1b[t];
    for (int k = 0; k < 3 * HD; k++)
        acc = fmaf(sh[k], r1w[k * 128 + t], acc);
    z[t] = (acc > 0.f) ? acc : 0.01f * acc;   // leaky_relu(0.01)
    __syncthreads();
    if (t < NO) {
        float o = r2b[t];
        #pragma unroll 4
        for (int k = 0; k < 128; k++)
            o = fmaf(z[k], r2w[k * NO + t], o);
        out[g * NO + t] = o;
    }
}

// -------------------------------- launcher ---------------------------------
extern "C" void kernel_launch(void* const* d_in, const int* in_sizes, int n_in,
                              void* d_out, int out_size)
{
    const float* x      = (const float*)d_in[0];
    const int*   ei     = (const int*)d_in[1];     // int32 (JAX default)
    const int*   batch  = (const int*)d_in[2];     // int32 (JAX default)
    const float* enc_w  = (const float*)d_in[3];
    const float* enc_b  = (const float*)d_in[4];
    const float* conv_w = (const float*)d_in[5];
    const float* conv_b = (const float*)d_in[6];
    const float* r1_w   = (const float*)d_in[7];
    const float* r1_b   = (const float*)d_in[8];
    const float* r2_w   = (const float*)d_in[9];
    const float* r2_b   = (const float*)d_in[10];
    float* out = (float*)d_out;

    float *h, *hw;
    cudaGetSymbolAddress((void**)&h,  g_h);
    cudaGetSymbolAddress((void**)&hw, g_hw);

    const int TB = 256;
    int gN = (NN + TB - 1) / TB;
    int gE = (NE + TB - 1) / TB;

    // graph structure
    k_init<<<gN, TB>>>();
    k_count_deg<<<gE, TB>>>(ei);
    k_dis<<<gN, TB>>>();
    k_scan_offsets<<<1, 1024>>>();
    k_fill_self<<<gN, TB>>>();
    k_fill_edges<<<gE, TB>>>(ei);
    k_batch_hist<<<gN, TB>>>(batch);
    k_scan_graphs<<<1, NG>>>();

    // encoder: h = x @ enc_w + enc_b
    {
        dim3 grid((NN + 127) / 128, HD / 128);
        k_sgemm<<<grid, 256>>>(x, enc_w, enc_b, h, NN, HD, FIN);
    }

    // conv layers
    for (int l = 0; l < NL; l++) {
        dim3 grid((NN + 127) / 128, HD / 128);
        k_sgemm<<<grid, 256>>>(h, conv_w + (size_t)l * HD * HD, nullptr, hw,
                               NN, HD, HD);
        k_aggregate<<<NN, HD>>>(conv_b + (size_t)l * HD);
    }

    // pooling + readout
    k_pool<<<NG, HD>>>();
    k_readout<<<NG, 128>>>(r1_w, r1_b, r2_w, r2_b, out);
}

// round 5
// speedup vs baseline: 2.0605x; 2.0605x over previous
#include <cuda_runtime.h>
#include <cuda_bf16.h>
#include <cstdint>

// ---------------------------------------------------------------------------
// GCN forward:  N=50000 nodes, E=800000 edges, F_IN=128, H=256, G=256, O=32, L=3
// edge_index / batch are int32 (JAX default config).
//
//   1. degree histogram (+self loops) -> dis = rsqrt(deg)
//   2. CSR-by-destination build, edge weight w = dis[s]*dis[d]
//   3. encoder GEMM (tf32 mma)  h = x @ enc_w + enc_b
//   4. 3x { hw = h @ conv_w[l] (tf32 mma);  h = CSR-aggregate(hw) + conv_b[l] }
//   5. sorted-batch pooling -> hg = [sum | max | mean]
//   6. readout MLP -> out
// ---------------------------------------------------------------------------

#define NN 50000
#define NE 800000
#define FIN 128
#define HD 256
#define NG 256
#define NO 32
#define NL 3
#define ETOT (NE + NN)
#define SCB 49          // ceil(50000/1024) scan blocks

// ----------------------------- device scratch ------------------------------
__device__ float g_h[(size_t)NN * HD];
__device__ float g_hw[(size_t)NN * HD];
__device__ int   g_counts[NN];
__device__ int   g_cursor[NN];
__device__ float g_dis[NN];
__device__ int   g_offsets[NN + 1];
__device__ int   g_part[SCB];
__device__ int   g_csr_src[ETOT];
__device__ float g_csr_w[ETOT];
__device__ int   g_gcount[NG];
__device__ int   g_gstart[NG + 1];
__device__ float g_hg[NG * 3 * HD];

// ------------------------------ setup kernels ------------------------------
__global__ void k_init() {
    int i = blockIdx.x * blockDim.x + threadIdx.x;
    if (i < NN) { g_counts[i] = 1; g_cursor[i] = 0; }   // count=1: self loop
    if (i < NG) g_gcount[i] = 0;
}

__global__ void k_count_deg(const int* __restrict__ ei) {
    int e = blockIdx.x * blockDim.x + threadIdx.x;
    if (e < NE) atomicAdd(&g_counts[ei[NE + e]], 1);
}

__global__ void k_dis() {
    int i = blockIdx.x * blockDim.x + threadIdx.x;
    if (i < NN) g_dis[i] = rsqrtf((float)g_counts[i]);
}

// ---- parallel scan: local inclusive per 1024-block, then partials ----
__global__ void __launch_bounds__(1024) k_scan_local() {
    __shared__ int sd[1024];
    int t = threadIdx.x;
    int i = blockIdx.x * 1024 + t;
    int v = (i < NN) ? g_counts[i] : 0;
    sd[t] = v;
    __syncthreads();
    #pragma unroll
    for (int off = 1; off < 1024; off <<= 1) {
        int tmp = (t >= off) ? sd[t - off] : 0;
        __syncthreads();
        if (t >= off) sd[t] += tmp;
        __syncthreads();
    }
    if (i < NN) g_offsets[i + 1] = sd[t];
    if (t == 1023) g_part[blockIdx.x] = sd[t];
}

__global__ void k_scan_part() {
    if (threadIdx.x == 0) {
        int running = 0;
        #pragma unroll
        for (int b = 0; b < SCB; b++) {
            int v = g_part[b];
            g_part[b] = running;
            running += v;
        }
        g_offsets[0] = 0;
    }
}

__global__ void __launch_bounds__(1024) k_scan_add() {
    int i = blockIdx.x * 1024 + threadIdx.x;
    if (i < NN) g_offsets[i + 1] += g_part[blockIdx.x];
}

__global__ void k_fill_self() {
    int i = blockIdx.x * blockDim.x + threadIdx.x;
    if (i < NN) {
        int pos = g_offsets[i] + atomicAdd(&g_cursor[i], 1);
        g_csr_src[pos] = i;
        float d = g_dis[i];
        g_csr_w[pos] = d * d;
    }
}

__global__ void k_fill_edges(const int* __restrict__ ei) {
    int e = blockIdx.x * blockDim.x + threadIdx.x;
    if (e < NE) {
        int s = ei[e];
        int d = ei[NE + e];
        int pos = g_offsets[d] + atomicAdd(&g_cursor[d], 1);
        g_csr_src[pos] = s;
        g_csr_w[pos] = g_dis[s] * g_dis[d];
    }
}

__global__ void k_batch_hist(const int* __restrict__ batch) {
    int i = blockIdx.x * blockDim.x + threadIdx.x;
    if (i < NN) atomicAdd(&g_gcount[batch[i]], 1);
}

__global__ void k_scan_graphs() {
    __shared__ int sd[NG];
    int t = threadIdx.x;
    sd[t] = g_gcount[t];
    __syncthreads();
    #pragma unroll
    for (int off = 1; off < NG; off <<= 1) {
        int tmp = (t >= off) ? sd[t - off] : 0;
        __syncthreads();
        if (t >= off) sd[t] += tmp;
        __syncthreads();
    }
    if (t == 0) g_gstart[0] = 0;
    g_gstart[t + 1] = sd[t];
}

// -------------------------- tf32 tensor-core GEMM --------------------------
// C[M,N] = A[M,K] @ B[K,N] (+ bias), row-major. Tile 128x128x16, 256 thr.
// 8 warps in a 4(M) x 2(N) grid, each warp 32x64, mma.sync m16n8k8 tf32.
// Smem K-major [16][136] (pad 8 -> stride 136 = conflict-free fragments).

__device__ __forceinline__ uint32_t f2tf32(float f) {
    uint32_t u;
    asm("cvt.rna.tf32.f32 %0, %1;" : "=r"(u) : "f"(f));
    return u;
}

__device__ __forceinline__ void mma_tf32(float* c, const uint32_t* a,
                                         uint32_t b0, uint32_t b1) {
    asm volatile(
        "mma.sync.aligned.m16n8k8.row.col.f32.tf32.tf32.f32 "
        "{%0,%1,%2,%3}, {%4,%5,%6,%7}, {%8,%9}, {%0,%1,%2,%3};"
        : "+f"(c[0]), "+f"(c[1]), "+f"(c[2]), "+f"(c[3])
        : "r"(a[0]), "r"(a[1]), "r"(a[2]), "r"(a[3]), "r"(b0), "r"(b1));
}

__global__ void __launch_bounds__(256) k_gemm_tf32(
    const float* __restrict__ A, const float* __restrict__ B,
    const float* __restrict__ bias, float* __restrict__ C,
    int M, int N, int K)
{
    __shared__ uint32_t As[2][16][136];
    __shared__ uint32_t Bs[2][16][136];

    int tid = threadIdx.x;
    int bm = blockIdx.x * 128;
    int bn = blockIdx.y * 128;

    int lane = tid & 31;
    int warp = tid >> 5;
    int tig  = lane & 3;        // thread-in-group (col of A frag / k of B frag)
    int grp  = lane >> 2;       // group id        (row of A frag / n of B frag)
    int wm   = (warp & 3) * 32; // warp row offset within tile
    int wn   = (warp >> 2) * 64;// warp col offset within tile

    // global-load coordinates (per thread)
    int ar  = bm + (tid >> 1);  if (ar >= M) ar = M - 1;
    int akq = (tid & 1) * 8;            // k sub-offset 0 or 8
    int bk  = tid >> 4;                 // 0..15
    int bc  = (tid & 15) * 8;           // 0..120

    const float* Ap = A + (size_t)ar * K + akq;
    const float* Bp = B + (size_t)bk * N + bn + bc;

    float acc[2][8][4];
    #pragma unroll
    for (int mt = 0; mt < 2; mt++)
        #pragma unroll
        for (int nt = 0; nt < 8; nt++)
            #pragma unroll
            for (int r = 0; r < 4; r++) acc[mt][nt][r] = 0.f;

    int KT = K >> 4;

    // prologue: load tile 0
    float4 rA0 = *(const float4*)(Ap);
    float4 rA1 = *(const float4*)(Ap + 4);
    float4 rB0 = *(const float4*)(Bp);
    float4 rB1 = *(const float4*)(Bp + 4);

    {
        int arow = tid >> 1;
        As[0][akq + 0][arow] = f2tf32(rA0.x);
        As[0][akq + 1][arow] = f2tf32(rA0.y);
        As[0][akq + 2][arow] = f2tf32(rA0.z);
        As[0][akq + 3][arow] = f2tf32(rA0.w);
        As[0][akq + 4][arow] = f2tf32(rA1.x);
        As[0][akq + 5][arow] = f2tf32(rA1.y);
        As[0][akq + 6][arow] = f2tf32(rA1.z);
        As[0][akq + 7][arow] = f2tf32(rA1.w);
        Bs[0][bk][bc + 0] = f2tf32(rB0.x);
        Bs[0][bk][bc + 1] = f2tf32(rB0.y);
        Bs[0][bk][bc + 2] = f2tf32(rB0.z);
        Bs[0][bk][bc + 3] = f2tf32(rB0.w);
        Bs[0][bk][bc + 4] = f2tf32(rB1.x);
        Bs[0][bk][bc + 5] = f2tf32(rB1.y);
        Bs[0][bk][bc + 6] = f2tf32(rB1.z);
        Bs[0][bk][bc + 7] = f2tf32(rB1.w);
    }
    __syncthreads();

    for (int kt = 0; kt < KT; kt++) {
        int cur = kt & 1;
        int nxt = cur ^ 1;
        // prefetch next tile (global -> regs) before compute
        if (kt + 1 < KT) {
            const float* Ap2 = Ap + (kt + 1) * 16;
            const float* Bp2 = Bp + (size_t)(kt + 1) * 16 * N;
            rA0 = *(const float4*)(Ap2);
            rA1 = *(const float4*)(Ap2 + 4);
            rB0 = *(const float4*)(Bp2);
            rB1 = *(const float4*)(Bp2 + 4);
        }

        #pragma unroll
        for (int kk = 0; kk < 16; kk += 8) {
            uint32_t a[2][4];
            #pragma unroll
            for (int mt = 0; mt < 2; mt++) {
                int rb = wm + mt * 16 + grp;
                a[mt][0] = As[cur][kk + tig][rb];
                a[mt][1] = As[cur][kk + tig][rb + 8];
                a[mt][2] = As[cur][kk + tig + 4][rb];
                a[mt][3] = As[cur][kk + tig + 4][rb + 8];
            }
            #pragma unroll
            for (int nt = 0; nt < 8; nt++) {
                int nb = wn + nt * 8 + grp;
                uint32_t b0 = Bs[cur][kk + tig][nb];
                uint32_t b1 = Bs[cur][kk + tig + 4][nb];
                mma_tf32(acc[0][nt], a[0], b0, b1);
                mma_tf32(acc[1][nt], a[1], b0, b1);
            }
        }

        if (kt + 1 < KT) {
            int arow = tid >> 1;
            As[nxt][akq + 0][arow] = f2tf32(rA0.x);
            As[nxt][akq + 1][arow] = f2tf32(rA0.y);
            As[nxt][akq + 2][arow] = f2tf32(rA0.z);
            As[nxt][akq + 3][arow] = f2tf32(rA0.w);
            As[nxt][akq + 4][arow] = f2tf32(rA1.x);
            As[nxt][akq + 5][arow] = f2tf32(rA1.y);
            As[nxt][akq + 6][arow] = f2tf32(rA1.z);
            As[nxt][akq + 7][arow] = f2tf32(rA1.w);
            Bs[nxt][bk][bc + 0] = f2tf32(rB0.x);
            Bs[nxt][bk][bc + 1] = f2tf32(rB0.y);
            Bs[nxt][bk][bc + 2] = f2tf32(rB0.z);
            Bs[nxt][bk][bc + 3] = f2tf32(rB0.w);
            Bs[nxt][bk][bc + 4] = f2tf32(rB1.x);
            Bs[nxt][bk][bc + 5] = f2tf32(rB1.y);
            Bs[nxt][bk][bc + 6] = f2tf32(rB1.z);
            Bs[nxt][bk][bc + 7] = f2tf32(rB1.w);
        }
        __syncthreads();
    }

    // epilogue
    #pragma unroll
    for (int mt = 0; mt < 2; mt++) {
        #pragma unroll
        for (int nt = 0; nt < 8; nt++) {
            int col = bn + wn + nt * 8 + tig * 2;
            float b0 = bias ? bias[col]     : 0.f;
            float b1 = bias ? bias[col + 1] : 0.f;
            int r0 = bm + wm + mt * 16 + grp;
            if (r0 < M) {
                float2 v = make_float2(acc[mt][nt][0] + b0, acc[mt][nt][1] + b1);
                *(float2*)(C + (size_t)r0 * N + col) = v;
            }
            int r1 = r0 + 8;
            if (r1 < M) {
                float2 v = make_float2(acc[mt][nt][2] + b0, acc[mt][nt][3] + b1);
                *(float2*)(C + (size_t)r1 * N + col) = v;
            }
        }
    }
}

// ----------------------------- CSR aggregation -----------------------------
// 256 threads = 4 groups of 64; each group handles one node, float4 per thread
__global__ void __launch_bounds__(256) k_aggregate(const float* __restrict__ bias) {
    int grpIdx = threadIdx.x >> 6;           // 0..3
    int t      = threadIdx.x & 63;           // float4 lane
    int i = blockIdx.x * 4 + grpIdx;
    if (i >= NN) return;
    int beg = g_offsets[i];
    int end = g_offsets[i + 1];
    float4 b4 = ((const float4*)bias)[t];
    float4 acc = b4;
    const float4* hw4 = (const float4*)g_hw;
    for (int e = beg; e < end; ++e) {
        int s   = __ldg(&g_csr_src[e]);
        float w = __ldg(&g_csr_w[e]);
        float4 v = __ldg(&hw4[(size_t)s * 64 + t]);
        acc.x = fmaf(w, v.x, acc.x);
        acc.y = fmaf(w, v.y, acc.y);
        acc.z = fmaf(w, v.z, acc.z);
        acc.w = fmaf(w, v.w, acc.w);
    }
    ((float4*)g_h)[(size_t)i * 64 + t] = acc;
}

// -------------------------------- pooling ----------------------------------
__global__ void __launch_bounds__(HD) k_pool() {
    int g = blockIdx.x;
    int f = threadIdx.x;
    int beg = g_gstart[g], end = g_gstart[g + 1];
    float s = 0.f, m = -3.402823e38f;
    for (int i = beg; i < end; ++i) {
        float v = g_h[(size_t)i * HD + f];
        s += v;
        m = fmaxf(m, v);
    }
    int cnt = end - beg;
    g_hg[g * 3 * HD + f]          = s;
    g_hg[g * 3 * HD + HD + f]     = (cnt > 0) ? m : 0.f;
    g_hg[g * 3 * HD + 2 * HD + f] = s / (float)(cnt > 0 ? cnt : 1);
}

// -------------------------------- readout ----------------------------------
__global__ void __launch_bounds__(128) k_readout(
    const float* __restrict__ r1w, const float* __restrict__ r1b,
    const float* __restrict__ r2w, const float* __restrict__ r2b,
    float* __restrict__ out)
{
    int g = blockIdx.x;
    int t = threadIdx.x;
    __shared__ float sh[3 * HD];
    __shared__ float z[128];
    for (int i = t; i < 3 * HD; i += 128) sh[i] = g_hg[g * 3 * HD + i];
    __syncthreads();
    float acc = r1b[t];
    for (int k = 0; k < 3 * HD; k++)
        acc = fmaf(sh[k], r1w[k * 128 + t], acc);
    z[t] = (acc > 0.f) ? acc : 0.01f * acc;   // leaky_relu(0.01)
    __syncthreads();
    if (t < NO) {
        float o = r2b[t];
        #pragma unroll 4
        for (int k = 0; k < 128; k++)
            o = fmaf(z[k], r2w[k * NO + t], o);
        out[g * NO + t] = o;
    }
}

// -------------------------------- launcher ---------------------------------
extern "C" void kernel_launch(void* const* d_in, const int* in_sizes, int n_in,
                              void* d_out, int out_size)
{
    const float* x      = (const float*)d_in[0];
    const int*   ei     = (const int*)d_in[1];
    const int*   batch  = (const int*)d_in[2];
    const float* enc_w  = (const float*)d_in[3];
    const float* enc_b  = (const float*)d_in[4];
    const float* conv_w = (const float*)d_in[5];
    const float* conv_b = (const float*)d_in[6];
    const float* r1_w   = (const float*)d_in[7];
    const float* r1_b   = (const float*)d_in[8];
    const float* r2_w   = (const float*)d_in[9];
    const float* r2_b   = (const float*)d_in[10];
    float* out = (float*)d_out;

    float *h, *hw;
    cudaGetSymbolAddress((void**)&h,  g_h);
    cudaGetSymbolAddress((void**)&hw, g_hw);

    const int TB = 256;
    int gN = (NN + TB - 1) / TB;
    int gE = (NE + TB - 1) / TB;

    // graph structure
    k_init<<<gN, TB>>>();
    k_count_deg<<<gE, TB>>>(ei);
    k_dis<<<gN, TB>>>();
    k_scan_local<<<SCB, 1024>>>();
    k_scan_part<<<1, 32>>>();
    k_scan_add<<<SCB, 1024>>>();
    k_fill_self<<<gN, TB>>>();
    k_fill_edges<<<gE, TB>>>(ei);
    k_batch_hist<<<gN, TB>>>(batch);
    k_scan_graphs<<<1, NG>>>();

    dim3 grid((NN + 127) / 128, HD / 128);

    // encoder: h = x @ enc_w + enc_b
    k_gemm_tf32<<<grid, 256>>>(x, enc_w, enc_b, h, NN, HD, FIN);

    // conv layers
    for (int l = 0; l < NL; l++) {
        k_gemm_tf32<<<grid, 256>>>(h, conv_w + (size_t)l * HD * HD, nullptr, hw,
                                   NN, HD, HD);
        k_aggregate<<<(NN + 3) / 4, 256>>>(conv_b + (size_t)l * HD);
    }

    // pooling + readout
    k_pool<<<NG, HD>>>();
    k_readout<<<NG, 128>>>(r1_w, r1_b, r2_w, r2_b, out);
}

// round 6
// speedup vs baseline: 2.0874x; 1.0131x over previous
#include <cuda_runtime.h>
#include <cuda_bf16.h>
#include <cstdint>

// ---------------------------------------------------------------------------
// GCN forward:  N=50000, E=800000, F_IN=128, H=256, G=256, O=32, L=3
// edge_index / batch are int32.
//
// Stream graph (captured):
//   origin: k_init ─┬─> encoder GEMM ─> batch_hist ─> scan_graphs ──┐
//                   └─(side)─> CSR build chain ──────────────────────┤
//   join ─> 3x { conv GEMM ; CSR aggregate } ─> pool ─> readout
// ---------------------------------------------------------------------------

#define NN 50000
#define NE 800000
#define FIN 128
#define HD 256
#define NG 256
#define NO 32
#define NL 3
#define ETOT (NE + NN)
#define SCB 49          // ceil(50000/1024) scan blocks

// ----------------------------- device scratch ------------------------------
__device__ float g_h[(size_t)NN * HD];
__device__ float g_hw[(size_t)NN * HD];
__device__ int   g_counts[NN];
__device__ int   g_cursor[NN];
__device__ float g_dis[NN];
__device__ int   g_offsets[NN + 1];
__device__ int   g_part[SCB];
__device__ int2  g_csr[ETOT];          // {src, bitcast(weight)}
__device__ int   g_gcount[NG];
__device__ int   g_gstart[NG + 1];
__device__ float g_hg[NG * 3 * HD];

// ------------------------------ setup kernels ------------------------------
__global__ void k_init() {
    int i = blockIdx.x * blockDim.x + threadIdx.x;
    if (i < NN) { g_counts[i] = 1; g_cursor[i] = 0; }   // count=1: self loop
    if (i < NG) g_gcount[i] = 0;
}

__global__ void k_count_deg(const int* __restrict__ ei) {
    int e = blockIdx.x * blockDim.x + threadIdx.x;
    if (e < NE) atomicAdd(&g_counts[ei[NE + e]], 1);
}

// local inclusive scan per 1024-block; also emits dis = rsqrt(count)
__global__ void __launch_bounds__(1024) k_scan_local() {
    __shared__ int sd[1024];
    int t = threadIdx.x;
    int i = blockIdx.x * 1024 + t;
    int v = 0;
    if (i < NN) {
        v = g_counts[i];
        g_dis[i] = rsqrtf((float)v);
    }
    sd[t] = v;
    __syncthreads();
    #pragma unroll
    for (int off = 1; off < 1024; off <<= 1) {
        int tmp = (t >= off) ? sd[t - off] : 0;
        __syncthreads();
        if (t >= off) sd[t] += tmp;
        __syncthreads();
    }
    if (i < NN) g_offsets[i + 1] = sd[t];
    if (t == 1023) g_part[blockIdx.x] = sd[t];
}

__global__ void k_scan_part() {
    if (threadIdx.x == 0) {
        int running = 0;
        #pragma unroll
        for (int b = 0; b < SCB; b++) {
            int v = g_part[b];
            g_part[b] = running;
            running += v;
        }
        g_offsets[0] = 0;
    }
}

__global__ void __launch_bounds__(1024) k_scan_add() {
    int i = blockIdx.x * 1024 + threadIdx.x;
    if (i < NN) g_offsets[i + 1] += g_part[blockIdx.x];
}

__global__ void k_fill_self() {
    int i = blockIdx.x * blockDim.x + threadIdx.x;
    if (i < NN) {
        int pos = g_offsets[i] + atomicAdd(&g_cursor[i], 1);
        float d = g_dis[i];
        g_csr[pos] = make_int2(i, __float_as_int(d * d));
    }
}

__global__ void k_fill_edges(const int* __restrict__ ei) {
    int e = blockIdx.x * blockDim.x + threadIdx.x;
    if (e < NE) {
        int s = ei[e];
        int d = ei[NE + e];
        int pos = g_offsets[d] + atomicAdd(&g_cursor[d], 1);
        g_csr[pos] = make_int2(s, __float_as_int(g_dis[s] * g_dis[d]));
    }
}

__global__ void k_batch_hist(const int* __restrict__ batch) {
    int i = blockIdx.x * blockDim.x + threadIdx.x;
    if (i < NN) atomicAdd(&g_gcount[batch[i]], 1);
}

__global__ void k_scan_graphs() {
    __shared__ int sd[NG];
    int t = threadIdx.x;
    sd[t] = g_gcount[t];
    __syncthreads();
    #pragma unroll
    for (int off = 1; off < NG; off <<= 1) {
        int tmp = (t >= off) ? sd[t - off] : 0;
        __syncthreads();
        if (t >= off) sd[t] += tmp;
        __syncthreads();
    }
    if (t == 0) g_gstart[0] = 0;
    g_gstart[t + 1] = sd[t];
}

// -------------------------- tf32 tensor-core GEMM --------------------------
__device__ __forceinline__ uint32_t f2tf32(float f) {
    uint32_t u;
    asm("cvt.rna.tf32.f32 %0, %1;" : "=r"(u) : "f"(f));
    return u;
}

__device__ __forceinline__ void mma_tf32(float* c, const uint32_t* a,
                                         uint32_t b0, uint32_t b1) {
    asm volatile(
        "mma.sync.aligned.m16n8k8.row.col.f32.tf32.tf32.f32 "
        "{%0,%1,%2,%3}, {%4,%5,%6,%7}, {%8,%9}, {%0,%1,%2,%3};"
        : "+f"(c[0]), "+f"(c[1]), "+f"(c[2]), "+f"(c[3])
        : "r"(a[0]), "r"(a[1]), "r"(a[2]), "r"(a[3]), "r"(b0), "r"(b1));
}

__global__ void __launch_bounds__(256) k_gemm_tf32(
    const float* __restrict__ A, const float* __restrict__ B,
    const float* __restrict__ bias, float* __restrict__ C,
    int M, int N, int K)
{
    __shared__ uint32_t As[2][16][136];
    __shared__ uint32_t Bs[2][16][136];

    int tid = threadIdx.x;
    int bm = blockIdx.x * 128;
    int bn = blockIdx.y * 128;

    int lane = tid & 31;
    int warp = tid >> 5;
    int tig  = lane & 3;
    int grp  = lane >> 2;
    int wm   = (warp & 3) * 32;
    int wn   = (warp >> 2) * 64;

    int ar  = bm + (tid >> 1);  if (ar >= M) ar = M - 1;
    int akq = (tid & 1) * 8;
    int bk  = tid >> 4;
    int bc  = (tid & 15) * 8;

    const float* Ap = A + (size_t)ar * K + akq;
    const float* Bp = B + (size_t)bk * N + bn + bc;

    float acc[2][8][4];
    #pragma unroll
    for (int mt = 0; mt < 2; mt++)
        #pragma unroll
        for (int nt = 0; nt < 8; nt++)
            #pragma unroll
            for (int r = 0; r < 4; r++) acc[mt][nt][r] = 0.f;

    int KT = K >> 4;

    float4 rA0 = *(const float4*)(Ap);
    float4 rA1 = *(const float4*)(Ap + 4);
    float4 rB0 = *(const float4*)(Bp);
    float4 rB1 = *(const float4*)(Bp + 4);

    {
        int arow = tid >> 1;
        As[0][akq + 0][arow] = f2tf32(rA0.x);
        As[0][akq + 1][arow] = f2tf32(rA0.y);
        As[0][akq + 2][arow] = f2tf32(rA0.z);
        As[0][akq + 3][arow] = f2tf32(rA0.w);
        As[0][akq + 4][arow] = f2tf32(rA1.x);
        As[0][akq + 5][arow] = f2tf32(rA1.y);
        As[0][akq + 6][arow] = f2tf32(rA1.z);
        As[0][akq + 7][arow] = f2tf32(rA1.w);
        Bs[0][bk][bc + 0] = f2tf32(rB0.x);
        Bs[0][bk][bc + 1] = f2tf32(rB0.y);
        Bs[0][bk][bc + 2] = f2tf32(rB0.z);
        Bs[0][bk][bc + 3] = f2tf32(rB0.w);
        Bs[0][bk][bc + 4] = f2tf32(rB1.x);
        Bs[0][bk][bc + 5] = f2tf32(rB1.y);
        Bs[0][bk][bc + 6] = f2tf32(rB1.z);
        Bs[0][bk][bc + 7] = f2tf32(rB1.w);
    }
    __syncthreads();

    for (int kt = 0; kt < KT; kt++) {
        int cur = kt & 1;
        int nxt = cur ^ 1;
        if (kt + 1 < KT) {
            const float* Ap2 = Ap + (kt + 1) * 16;
            const float* Bp2 = Bp + (size_t)(kt + 1) * 16 * N;
            rA0 = *(const float4*)(Ap2);
            rA1 = *(const float4*)(Ap2 + 4);
            rB0 = *(const float4*)(Bp2);
            rB1 = *(const float4*)(Bp2 + 4);
        }

        #pragma unroll
        for (int kk = 0; kk < 16; kk += 8) {
            uint32_t a[2][4];
            #pragma unroll
            for (int mt = 0; mt < 2; mt++) {
                int rb = wm + mt * 16 + grp;
                a[mt][0] = As[cur][kk + tig][rb];
                a[mt][1] = As[cur][kk + tig][rb + 8];
                a[mt][2] = As[cur][kk + tig + 4][rb];
                a[mt][3] = As[cur][kk + tig + 4][rb + 8];
            }
            #pragma unroll
            for (int nt = 0; nt < 8; nt++) {
                int nb = wn + nt * 8 + grp;
                uint32_t b0 = Bs[cur][kk + tig][nb];
                uint32_t b1 = Bs[cur][kk + tig + 4][nb];
                mma_tf32(acc[0][nt], a[0], b0, b1);
                mma_tf32(acc[1][nt], a[1], b0, b1);
            }
        }

        if (kt + 1 < KT) {
            int arow = tid >> 1;
            As[nxt][akq + 0][arow] = f2tf32(rA0.x);
            As[nxt][akq + 1][arow] = f2tf32(rA0.y);
            As[nxt][akq + 2][arow] = f2tf32(rA0.z);
            As[nxt][akq + 3][arow] = f2tf32(rA0.w);
            As[nxt][akq + 4][arow] = f2tf32(rA1.x);
            As[nxt][akq + 5][arow] = f2tf32(rA1.y);
            As[nxt][akq + 6][arow] = f2tf32(rA1.z);
            As[nxt][akq + 7][arow] = f2tf32(rA1.w);
            Bs[nxt][bk][bc + 0] = f2tf32(rB0.x);
            Bs[nxt][bk][bc + 1] = f2tf32(rB0.y);
            Bs[nxt][bk][bc + 2] = f2tf32(rB0.z);
            Bs[nxt][bk][bc + 3] = f2tf32(rB0.w);
            Bs[nxt][bk][bc + 4] = f2tf32(rB1.x);
            Bs[nxt][bk][bc + 5] = f2tf32(rB1.y);
            Bs[nxt][bk][bc + 6] = f2tf32(rB1.z);
            Bs[nxt][bk][bc + 7] = f2tf32(rB1.w);
        }
        __syncthreads();
    }

    #pragma unroll
    for (int mt = 0; mt < 2; mt++) {
        #pragma unroll
        for (int nt = 0; nt < 8; nt++) {
            int col = bn + wn + nt * 8 + tig * 2;
            float b0 = bias ? bias[col]     : 0.f;
            float b1 = bias ? bias[col + 1] : 0.f;
            int r0 = bm + wm + mt * 16 + grp;
            if (r0 < M) {
                float2 v = make_float2(acc[mt][nt][0] + b0, acc[mt][nt][1] + b1);
                *(float2*)(C + (size_t)r0 * N + col) = v;
            }
            int r1 = r0 + 8;
            if (r1 < M) {
                float2 v = make_float2(acc[mt][nt][2] + b0, acc[mt][nt][3] + b1);
                *(float2*)(C + (size_t)r1 * N + col) = v;
            }
        }
    }
}

// ----------------------------- CSR aggregation -----------------------------
// 4 nodes/block; 64 threads/node; float4/thread; 2-way unrolled dual-acc.
__global__ void __launch_bounds__(256) k_aggregate(const float* __restrict__ bias) {
    int grpIdx = threadIdx.x >> 6;
    int t      = threadIdx.x & 63;
    int i = blockIdx.x * 4 + grpIdx;
    if (i >= NN) return;
    int beg = g_offsets[i];
    int end = g_offsets[i + 1];
    float4 acc  = ((const float4*)bias)[t];
    float4 acc2 = make_float4(0.f, 0.f, 0.f, 0.f);
    const float4* hw4 = (const float4*)g_hw;
    int e = beg;
    for (; e + 2 <= end; e += 2) {
        int2 p0 = __ldg(&g_csr[e]);
        int2 p1 = __ldg(&g_csr[e + 1]);
        float w0 = __int_as_float(p0.y);
        float w1 = __int_as_float(p1.y);
        float4 v0 = __ldg(&hw4[(size_t)p0.x * 64 + t]);
        float4 v1 = __ldg(&hw4[(size_t)p1.x * 64 + t]);
        acc.x  = fmaf(w0, v0.x, acc.x);  acc.y  = fmaf(w0, v0.y, acc.y);
        acc.z  = fmaf(w0, v0.z, acc.z);  acc.w  = fmaf(w0, v0.w, acc.w);
        acc2.x = fmaf(w1, v1.x, acc2.x); acc2.y = fmaf(w1, v1.y, acc2.y);
        acc2.z = fmaf(w1, v1.z, acc2.z); acc2.w = fmaf(w1, v1.w, acc2.w);
    }
    if (e < end) {
        int2 p = __ldg(&g_csr[e]);
        float w = __int_as_float(p.y);
        float4 v = __ldg(&hw4[(size_t)p.x * 64 + t]);
        acc.x = fmaf(w, v.x, acc.x);  acc.y = fmaf(w, v.y, acc.y);
        acc.z = fmaf(w, v.z, acc.z);  acc.w = fmaf(w, v.w, acc.w);
    }
    acc.x += acc2.x; acc.y += acc2.y; acc.z += acc2.z; acc.w += acc2.w;
    ((float4*)g_h)[(size_t)i * 64 + t] = acc;
}

// -------------------------------- pooling ----------------------------------
__global__ void __launch_bounds__(HD) k_pool() {
    int g = blockIdx.x;
    int f = threadIdx.x;
    int beg = g_gstart[g], end = g_gstart[g + 1];
    float s = 0.f, m = -3.402823e38f;
    for (int i = beg; i < end; ++i) {
        float v = g_h[(size_t)i * HD + f];
        s += v;
        m = fmaxf(m, v);
    }
    int cnt = end - beg;
    g_hg[g * 3 * HD + f]          = s;
    g_hg[g * 3 * HD + HD + f]     = (cnt > 0) ? m : 0.f;
    g_hg[g * 3 * HD + 2 * HD + f] = s / (float)(cnt > 0 ? cnt : 1);
}

// -------------------------------- readout ----------------------------------
__global__ void __launch_bounds__(128) k_readout(
    const float* __restrict__ r1w, const float* __restrict__ r1b,
    const float* __restrict__ r2w, const float* __restrict__ r2b,
    float* __restrict__ out)
{
    int g = blockIdx.x;
    int t = threadIdx.x;
    __shared__ float sh[3 * HD];
    __shared__ float z[128];
    for (int i = t; i < 3 * HD; i += 128) sh[i] = g_hg[g * 3 * HD + i];
    __syncthreads();
    float acc = r1b[t];
    for (int k = 0; k < 3 * HD; k++)
        acc = fmaf(sh[k], r1w[k * 128 + t], acc);
    z[t] = (acc > 0.f) ? acc : 0.01f * acc;
    __syncthreads();
    if (t < NO) {
        float o = r2b[t];
        #pragma unroll 4
        for (int k = 0; k < 128; k++)
            o = fmaf(z[k], r2w[k * NO + t], o);
        out[g * NO + t] = o;
    }
}

// -------------------------------- launcher ---------------------------------
extern "C" void kernel_launch(void* const* d_in, const int* in_sizes, int n_in,
                              void* d_out, int out_size)
{
    const float* x      = (const float*)d_in[0];
    const int*   ei     = (const int*)d_in[1];
    const int*   batch  = (const int*)d_in[2];
    const float* enc_w  = (const float*)d_in[3];
    const float* enc_b  = (const float*)d_in[4];
    const float* conv_w = (const float*)d_in[5];
    const float* conv_b = (const float*)d_in[6];
    const float* r1_w   = (const float*)d_in[7];
    const float* r1_b   = (const float*)d_in[8];
    const float* r2_w   = (const float*)d_in[9];
    const float* r2_b   = (const float*)d_in[10];
    float* out = (float*)d_out;

    float *h, *hw;
    cudaGetSymbolAddress((void**)&h,  g_h);
    cudaGetSymbolAddress((void**)&hw, g_hw);

    static cudaStream_t s_side = nullptr;
    static cudaEvent_t  ev_fork = nullptr, ev_join = nullptr;
    if (!s_side) {
        cudaStreamCreateWithFlags(&s_side, cudaStreamNonBlocking);
        cudaEventCreateWithFlags(&ev_fork, cudaEventDisableTiming);
        cudaEventCreateWithFlags(&ev_join, cudaEventDisableTiming);
    }

    const int TB = 256;
    int gN = (NN + TB - 1) / TB;
    int gE = (NE + TB - 1) / TB;
    dim3 grid((NN + 127) / 128, HD / 128);

    // init on origin stream, then fork CSR chain to side stream
    k_init<<<gN, TB>>>();
    cudaEventRecord(ev_fork, 0);
    cudaStreamWaitEvent(s_side, ev_fork, 0);

    // side: CSR build chain
    k_count_deg<<<gE, TB, 0, s_side>>>(ei);
    k_scan_local<<<SCB, 1024, 0, s_side>>>();
    k_scan_part<<<1, 32, 0, s_side>>>();
    k_scan_add<<<SCB, 1024, 0, s_side>>>();
    k_fill_self<<<gN, TB, 0, s_side>>>();
    k_fill_edges<<<gE, TB, 0, s_side>>>(ei);
    cudaEventRecord(ev_join, s_side);

    // origin (overlapped): encoder GEMM + batch pooling setup
    k_gemm_tf32<<<grid, 256>>>(x, enc_w, enc_b, h, NN, HD, FIN);
    k_batch_hist<<<gN, TB>>>(batch);
    k_scan_graphs<<<1, NG>>>();

    // join
    cudaStreamWaitEvent(0, ev_join, 0);

    // conv layers
    for (int l = 0; l < NL; l++) {
        k_gemm_tf32<<<grid, 256>>>(h, conv_w + (size_t)l * HD * HD, nullptr, hw,
                                   NN, HD, HD);
        k_aggregate<<<(NN + 3) / 4, 256>>>(conv_b + (size_t)l * HD);
    }

    // pooling + readout
    k_pool<<<NG, HD>>>();
    k_readout<<<NG, 128>>>(r1_w, r1_b, r2_w, r2_b, out);
}

// round 8
// speedup vs baseline: 2.4938x; 1.1947x over previous
#include <cuda_runtime.h>
#include <cuda_fp16.h>
#include <cstdint>

// ---------------------------------------------------------------------------
// GCN forward:  N=50000, E=800000, F_IN=128, H=256, G=256, O=32, L=3
// edge_index / batch are int32.
//
// GEMMs: mma.sync.m16n8k16 fp16 inputs / fp32 accumulate (sm_100 ISA-safe;
// tcgen05 is rejected by the harness's sm_100 ptxas target).
// Weights pre-packed once per launch into half2 k-pair layout [K/2][256].
// ---------------------------------------------------------------------------

#define NN 50000
#define NE 800000
#define FIN 128
#define HD 256
#define NG 256
#define NO 32
#define NL 3
#define ETOT (NE + NN)
#define SCB 49

// ----------------------------- device scratch ------------------------------
__device__ float    g_h[(size_t)NN * HD];
__device__ float    g_hw[(size_t)NN * HD];
__device__ int      g_counts[NN];
__device__ int      g_cursor[NN];
__device__ float    g_dis[NN];
__device__ int      g_offsets[NN + 1];
__device__ int      g_part[SCB];
__device__ int2     g_csr[ETOT];
__device__ int      g_gcount[NG];
__device__ int      g_gstart[NG + 1];
__device__ float    g_hg[NG * 3 * HD];
__device__ uint32_t g_wp_enc[(FIN / 2) * HD];        // half2(W[2p][n],W[2p+1][n])
__device__ uint32_t g_wp_conv[NL * (HD / 2) * HD];

// ------------------------------ setup kernels ------------------------------
__global__ void k_init() {
    int i = blockIdx.x * blockDim.x + threadIdx.x;
    if (i < NN) { g_counts[i] = 1; g_cursor[i] = 0; }
    if (i < NG) g_gcount[i] = 0;
}

__global__ void k_count_deg(const int* __restrict__ ei) {
    int e = blockIdx.x * blockDim.x + threadIdx.x;
    if (e < NE) atomicAdd(&g_counts[ei[NE + e]], 1);
}

__global__ void __launch_bounds__(1024) k_scan_local() {
    __shared__ int sd[1024];
    int t = threadIdx.x;
    int i = blockIdx.x * 1024 + t;
    int v = 0;
    if (i < NN) {
        v = g_counts[i];
        g_dis[i] = rsqrtf((float)v);
    }
    sd[t] = v;
    __syncthreads();
    #pragma unroll
    for (int off = 1; off < 1024; off <<= 1) {
        int tmp = (t >= off) ? sd[t - off] : 0;
        __syncthreads();
        if (t >= off) sd[t] += tmp;
        __syncthreads();
    }
    if (i < NN) g_offsets[i + 1] = sd[t];
    if (t == 1023) g_part[blockIdx.x] = sd[t];
}

__global__ void k_scan_part() {
    if (threadIdx.x == 0) {
        int running = 0;
        #pragma unroll
        for (int b = 0; b < SCB; b++) {
            int v = g_part[b];
            g_part[b] = running;
            running += v;
        }
        g_offsets[0] = 0;
    }
}

__global__ void __launch_bounds__(1024) k_scan_add() {
    int i = blockIdx.x * 1024 + threadIdx.x;
    if (i < NN) g_offsets[i + 1] += g_part[blockIdx.x];
}

__global__ void k_fill_self() {
    int i = blockIdx.x * blockDim.x + threadIdx.x;
    if (i < NN) {
        int pos = g_offsets[i] + atomicAdd(&g_cursor[i], 1);
        float d = g_dis[i];
        g_csr[pos] = make_int2(i, __float_as_int(d * d));
    }
}

__global__ void k_fill_edges(const int* __restrict__ ei) {
    int e = blockIdx.x * blockDim.x + threadIdx.x;
    if (e < NE) {
        int s = ei[e];
        int d = ei[NE + e];
        int pos = g_offsets[d] + atomicAdd(&g_cursor[d], 1);
        g_csr[pos] = make_int2(s, __float_as_int(g_dis[s] * g_dis[d]));
    }
}

__global__ void k_batch_hist(const int* __restrict__ batch) {
    int i = blockIdx.x * blockDim.x + threadIdx.x;
    if (i < NN) atomicAdd(&g_gcount[batch[i]], 1);
}

__global__ void k_scan_graphs() {
    __shared__ int sd[NG];
    int t = threadIdx.x;
    sd[t] = g_gcount[t];
    __syncthreads();
    #pragma unroll
    for (int off = 1; off < NG; off <<= 1) {
        int tmp = (t >= off) ? sd[t - off] : 0;
        __syncthreads();
        if (t >= off) sd[t] += tmp;
        __syncthreads();
    }
    if (t == 0) g_gstart[0] = 0;
    g_gstart[t + 1] = sd[t];
}

// -------------- weight pack: fp32 [K][256] -> half2 [K/2][256] --------------
__global__ void k_pack_w(const float* __restrict__ enc_w,
                         const float* __restrict__ conv_w) {
    int i = blockIdx.x * blockDim.x + threadIdx.x;
    const int NE_ = (FIN / 2) * HD;                  // 16384
    const int NC_ = NL * (HD / 2) * HD;              // 98304
    if (i < NE_) {
        int p = i / HD, n = i % HD;
        __half2 h = __floats2half2_rn(enc_w[(2 * p) * HD + n],
                                      enc_w[(2 * p + 1) * HD + n]);
        g_wp_enc[i] = *reinterpret_cast<uint32_t*>(&h);
    }
    int j = i - NE_;
    if (j >= 0 && j < NC_) {
        int l = j / ((HD / 2) * HD);
        int r = j % ((HD / 2) * HD);
        int p = r / HD, n = r % HD;
        const float* W = conv_w + (size_t)l * HD * HD;
        __half2 h = __floats2half2_rn(W[(2 * p) * HD + n],
                                      W[(2 * p + 1) * HD + n]);
        g_wp_conv[j] = *reinterpret_cast<uint32_t*>(&h);
    }
}

// ----------------------- fp16 tensor-core GEMM ------------------------------
// C[M,256] = A[M,K] @ W[K,256] (+bias). Tile 128x128x16, 256 thr, 8 warps 4x2.
// Smem: k-pair-major uint32 [8][136] per buffer (half2 of k=2p,2p+1).
__device__ __forceinline__ void mma_f16(float* c, const uint32_t* a,
                                        uint32_t b0, uint32_t b1) {
    asm volatile(
        "mma.sync.aligned.m16n8k16.row.col.f32.f16.f16.f32 "
        "{%0,%1,%2,%3}, {%4,%5,%6,%7}, {%8,%9}, {%0,%1,%2,%3};"
        : "+f"(c[0]), "+f"(c[1]), "+f"(c[2]), "+f"(c[3])
        : "r"(a[0]), "r"(a[1]), "r"(a[2]), "r"(a[3]), "r"(b0), "r"(b1));
}

__global__ void __launch_bounds__(256) k_gemm_f16(
    const float* __restrict__ A, const uint32_t* __restrict__ Wp,
    const float* __restrict__ bias, float* __restrict__ C,
    int M, int K)
{
    __shared__ uint32_t As[2][8][136];
    __shared__ uint32_t Bs[2][8][136];

    int tid = threadIdx.x;
    int bm = blockIdx.x * 128;
    int bn = blockIdx.y * 128;

    int lane = tid & 31;
    int warp = tid >> 5;
    int tig  = lane & 3;
    int grp  = lane >> 2;
    int wm   = (warp & 3) * 32;
    int wn   = (warp >> 2) * 64;

    // A loader: row = tid>>1 (0..127), 8 floats from k-offset (tid&1)*8
    int ar  = bm + (tid >> 1);  if (ar >= M) ar = M - 1;
    int akq = (tid & 1) * 8;        // float k offset
    int ap2 = akq >> 1;             // k-pair offset (0 or 4)
    // B loader: k-pair row = tid>>5 (0..7), 4 uint32 cols from (tid&31)*4
    int bk  = tid >> 5;
    int bc  = (tid & 31) * 4;

    const float*    Apt = A + (size_t)ar * K + akq;
    const uint32_t* Bpt = Wp + (size_t)bk * HD + bn + bc;

    float acc[2][8][4];
    #pragma unroll
    for (int mt = 0; mt < 2; mt++)
        #pragma unroll
        for (int nt = 0; nt < 8; nt++)
            #pragma unroll
            for (int r = 0; r < 4; r++) acc[mt][nt][r] = 0.f;

    int KT = K >> 4;                // 16-k tiles

    // prologue: tile 0
    float4 rA0 = *(const float4*)(Apt);
    float4 rA1 = *(const float4*)(Apt + 4);
    uint4  rB  = *(const uint4*)(Bpt);

    {
        int arow = tid >> 1;
        __half2 h0 = __floats2half2_rn(rA0.x, rA0.y);
        __half2 h1 = __floats2half2_rn(rA0.z, rA0.w);
        __half2 h2 = __floats2half2_rn(rA1.x, rA1.y);
        __half2 h3 = __floats2half2_rn(rA1.z, rA1.w);
        As[0][ap2 + 0][arow] = *reinterpret_cast<uint32_t*>(&h0);
        As[0][ap2 + 1][arow] = *reinterpret_cast<uint32_t*>(&h1);
        As[0][ap2 + 2][arow] = *reinterpret_cast<uint32_t*>(&h2);
        As[0][ap2 + 3][arow] = *reinterpret_cast<uint32_t*>(&h3);
        Bs[0][bk][bc + 0] = rB.x;
        Bs[0][bk][bc + 1] = rB.y;
        Bs[0][bk][bc + 2] = rB.z;
        Bs[0][bk][bc + 3] = rB.w;
    }
    __syncthreads();

    for (int kt = 0; kt < KT; kt++) {
        int cur = kt & 1;
        int nxt = cur ^ 1;
        if (kt + 1 < KT) {
            const float*    Ap2p = Apt + (kt + 1) * 16;
            const uint32_t* Bp2p = Bpt + (size_t)(kt + 1) * 8 * HD;
            rA0 = *(const float4*)(Ap2p);
            rA1 = *(const float4*)(Ap2p + 4);
            rB  = *(const uint4*)(Bp2p);
        }

        uint32_t a[2][4];
        #pragma unroll
        for (int mt = 0; mt < 2; mt++) {
            int rb = wm + mt * 16 + grp;
            a[mt][0] = As[cur][tig][rb];
            a[mt][1] = As[cur][tig][rb + 8];
            a[mt][2] = As[cur][tig + 4][rb];
            a[mt][3] = As[cur][tig + 4][rb + 8];
        }
        #pragma unroll
        for (int nt = 0; nt < 8; nt++) {
            int nb = wn + nt * 8 + grp;
            uint32_t b0 = Bs[cur][tig][nb];
            uint32_t b1 = Bs[cur][tig + 4][nb];
            mma_f16(acc[0][nt], a[0], b0, b1);
            mma_f16(acc[1][nt], a[1], b0, b1);
        }

        if (kt + 1 < KT) {
            int arow = tid >> 1;
            __half2 h0 = __floats2half2_rn(rA0.x, rA0.y);
            __half2 h1 = __floats2half2_rn(rA0.z, rA0.w);
            __half2 h2 = __floats2half2_rn(rA1.x, rA1.y);
            __half2 h3 = __floats2half2_rn(rA1.z, rA1.w);
            As[nxt][ap2 + 0][arow] = *reinterpret_cast<uint32_t*>(&h0);
            As[nxt][ap2 + 1][arow] = *reinterpret_cast<uint32_t*>(&h1);
            As[nxt][ap2 + 2][arow] = *reinterpret_cast<uint32_t*>(&h2);
            As[nxt][ap2 + 3][arow] = *reinterpret_cast<uint32_t*>(&h3);
            Bs[nxt][bk][bc + 0] = rB.x;
            Bs[nxt][bk][bc + 1] = rB.y;
            Bs[nxt][bk][bc + 2] = rB.z;
            Bs[nxt][bk][bc + 3] = rB.w;
        }
        __syncthreads();
    }

    // epilogue
    #pragma unroll
    for (int mt = 0; mt < 2; mt++) {
        #pragma unroll
        for (int nt = 0; nt < 8; nt++) {
            int col = bn + wn + nt * 8 + tig * 2;
            float b0 = bias ? bias[col]     : 0.f;
            float b1 = bias ? bias[col + 1] : 0.f;
            int r0 = bm + wm + mt * 16 + grp;
            if (r0 < M) {
                float2 v = make_float2(acc[mt][nt][0] + b0, acc[mt][nt][1] + b1);
                *(float2*)(C + (size_t)r0 * HD + col) = v;
            }
            int r1 = r0 + 8;
            if (r1 < M) {
                float2 v = make_float2(acc[mt][nt][2] + b0, acc[mt][nt][3] + b1);
                *(float2*)(C + (size_t)r1 * HD + col) = v;
            }
        }
    }
}

// ----------------------------- CSR aggregation -----------------------------
__global__ void __launch_bounds__(256) k_aggregate(const float* __restrict__ bias) {
    int grpIdx = threadIdx.x >> 6;
    int t      = threadIdx.x & 63;
    int i = blockIdx.x * 4 + grpIdx;
    if (i >= NN) return;
    int beg = g_offsets[i];
    int end = g_offsets[i + 1];
    float4 acc  = ((const float4*)bias)[t];
    float4 acc2 = make_float4(0.f, 0.f, 0.f, 0.f);
    const float4* hw4 = (const float4*)g_hw;
    int e = beg;
    for (; e + 2 <= end; e += 2) {
        int2 p0 = __ldg(&g_csr[e]);
        int2 p1 = __ldg(&g_csr[e + 1]);
        float w0 = __int_as_float(p0.y);
        float w1 = __int_as_float(p1.y);
        float4 v0 = __ldg(&hw4[(size_t)p0.x * 64 + t]);
        float4 v1 = __ldg(&hw4[(size_t)p1.x * 64 + t]);
        acc.x  = fmaf(w0, v0.x, acc.x);  acc.y  = fmaf(w0, v0.y, acc.y);
        acc.z  = fmaf(w0, v0.z, acc.z);  acc.w  = fmaf(w0, v0.w, acc.w);
        acc2.x = fmaf(w1, v1.x, acc2.x); acc2.y = fmaf(w1, v1.y, acc2.y);
        acc2.z = fmaf(w1, v1.z, acc2.z); acc2.w = fmaf(w1, v1.w, acc2.w);
    }
    if (e < end) {
        int2 p = __ldg(&g_csr[e]);
        float w = __int_as_float(p.y);
        float4 v = __ldg(&hw4[(size_t)p.x * 64 + t]);
        acc.x = fmaf(w, v.x, acc.x);  acc.y = fmaf(w, v.y, acc.y);
        acc.z = fmaf(w, v.z, acc.z);  acc.w = fmaf(w, v.w, acc.w);
    }
    acc.x += acc2.x; acc.y += acc2.y; acc.z += acc2.z; acc.w += acc2.w;
    ((float4*)g_h)[(size_t)i * 64 + t] = acc;
}

// -------------------------------- pooling ----------------------------------
__global__ void __launch_bounds__(HD) k_pool() {
    int g = blockIdx.x;
    int f = threadIdx.x;
    int beg = g_gstart[g], end = g_gstart[g + 1];
    float s = 0.f, m = -3.402823e38f;
    for (int i = beg; i < end; ++i) {
        float v = g_h[(size_t)i * HD + f];
        s += v;
        m = fmaxf(m, v);
    }
    int cnt = end - beg;
    g_hg[g * 3 * HD + f]          = s;
    g_hg[g * 3 * HD + HD + f]     = (cnt > 0) ? m : 0.f;
    g_hg[g * 3 * HD + 2 * HD + f] = s / (float)(cnt > 0 ? cnt : 1);
}

// -------------------------------- readout ----------------------------------
__global__ void __launch_bounds__(128) k_readout(
    const float* __restrict__ r1w, const float* __restrict__ r1b,
    const float* __restrict__ r2w, const float* __restrict__ r2b,
    float* __restrict__ out)
{
    int g = blockIdx.x;
    int t = threadIdx.x;
    __shared__ float sh[3 * HD];
    __shared__ float z[128];
    for (int i = t; i < 3 * HD; i += 128) sh[i] = g_hg[g * 3 * HD + i];
    __syncthreads();
    float acc = r1b[t];
    for (int k = 0; k < 3 * HD; k++)
        acc = fmaf(sh[k], r1w[k * 128 + t], acc);
    z[t] = (acc > 0.f) ? acc : 0.01f * acc;
    __syncthreads();
    if (t < NO) {
        float o = r2b[t];
        #pragma unroll 4
        for (int k = 0; k < 128; k++)
            o = fmaf(z[k], r2w[k * NO + t], o);
        out[g * NO + t] = o;
    }
}

// -------------------------------- launcher ---------------------------------
extern "C" void kernel_launch(void* const* d_in, const int* in_sizes, int n_in,
                              void* d_out, int out_size)
{
    const float* x      = (const float*)d_in[0];
    const int*   ei     = (const int*)d_in[1];
    const int*   batch  = (const int*)d_in[2];
    const float* enc_w  = (const float*)d_in[3];
    const float* enc_b  = (const float*)d_in[4];
    const float* conv_w = (const float*)d_in[5];
    const float* conv_b = (const float*)d_in[6];
    const float* r1_w   = (const float*)d_in[7];
    const float* r1_b   = (const float*)d_in[8];
    const float* r2_w   = (const float*)d_in[9];
    const float* r2_b   = (const float*)d_in[10];
    float* out = (float*)d_out;

    float *h, *hw;
    uint32_t *wp_enc, *wp_conv;
    cudaGetSymbolAddress((void**)&h,  g_h);
    cudaGetSymbolAddress((void**)&hw, g_hw);
    cudaGetSymbolAddress((void**)&wp_enc,  g_wp_enc);
    cudaGetSymbolAddress((void**)&wp_conv, g_wp_conv);

    static cudaStream_t s_side = nullptr;
    static cudaEvent_t  ev_fork = nullptr, ev_join = nullptr;
    if (!s_side) {
        cudaStreamCreateWithFlags(&s_side, cudaStreamNonBlocking);
        cudaEventCreateWithFlags(&ev_fork, cudaEventDisableTiming);
        cudaEventCreateWithFlags(&ev_join, cudaEventDisableTiming);
    }

    const int TB = 256;
    int gN = (NN + TB - 1) / TB;
    int gE = (NE + TB - 1) / TB;
    dim3 grid((NN + 127) / 128, HD / 128);

    // init on origin stream, then fork CSR chain to side stream
    k_init<<<gN, TB>>>();
    cudaEventRecord(ev_fork, 0);
    cudaStreamWaitEvent(s_side, ev_fork, 0);

    // side: CSR build chain
    k_count_deg<<<gE, TB, 0, s_side>>>(ei);
    k_scan_local<<<SCB, 1024, 0, s_side>>>();
    k_scan_part<<<1, 32, 0, s_side>>>();
    k_scan_add<<<SCB, 1024, 0, s_side>>>();
    k_fill_self<<<gN, TB, 0, s_side>>>();
    k_fill_edges<<<gE, TB, 0, s_side>>>(ei);
    cudaEventRecord(ev_join, s_side);

    // origin: weight pack, encoder GEMM, pooling setup (overlapped with side)
    {
        int total = (FIN / 2) * HD + NL * (HD / 2) * HD;
        k_pack_w<<<(total + TB - 1) / TB, TB>>>(enc_w, conv_w);
    }
    k_gemm_f16<<<grid, 256>>>(x, wp_enc, enc_b, h, NN, FIN);
    k_batch_hist<<<gN, TB>>>(batch);
    k_scan_graphs<<<1, NG>>>();

    // join
    cudaStreamWaitEvent(0, ev_join, 0);

    // conv layers
    for (int l = 0; l < NL; l++) {
        k_gemm_f16<<<grid, 256>>>(h, wp_conv + (size_t)l * (HD / 2) * HD,
                                  nullptr, hw, NN, HD);
        k_aggregate<<<(NN + 3) / 4, 256>>>(conv_b + (size_t)l * HD);
    }

    // pooling + readout
    k_pool<<<NG, HD>>>();
    k_readout<<<NG, 128>>>(r1_w, r1_b, r2_w, r2_b, out);
}

// round 9
// speedup vs baseline: 2.9237x; 1.1724x over previous
#include <cuda_runtime.h>
#include <cuda_fp16.h>
#include <cstdint>

// ---------------------------------------------------------------------------
// GCN forward:  N=50000, E=800000, F_IN=128, H=256, G=256, O=32, L=3
// edge_index / batch are int32.
//
// GEMMs: mma.sync.m16n8k16 fp16/fp32-acc. Conv GEMMs write hw in *fp16*
// (halves the L2-bound CSR gather traffic); aggregation accumulates fp32.
// ---------------------------------------------------------------------------

#define NN 50000
#define NE 800000
#define FIN 128
#define HD 256
#define NG 256
#define NO 32
#define NL 3
#define ETOT (NE + NN)
#define SCB 49

// ----------------------------- device scratch ------------------------------
__device__ float    g_h[(size_t)NN * HD];
__device__ __half   g_hwh[(size_t)NN * HD];          // fp16 hw (conv GEMM out)
__device__ int      g_counts[NN];
__device__ int      g_cursor[NN];
__device__ float    g_dis[NN];
__device__ int      g_offsets[NN + 1];
__device__ int      g_part[SCB];
__device__ int2     g_csr[ETOT];
__device__ int      g_gcount[NG];
__device__ int      g_gstart[NG + 1];
__device__ float    g_hg[NG * 3 * HD];
__device__ uint32_t g_wp_enc[(FIN / 2) * HD];        // half2(W[2p][n],W[2p+1][n])
__device__ uint32_t g_wp_conv[NL * (HD / 2) * HD];

// ------------------------------ setup kernels ------------------------------
__global__ void k_init() {
    int i = blockIdx.x * blockDim.x + threadIdx.x;
    if (i < NN) { g_counts[i] = 1; g_cursor[i] = 0; }
    if (i < NG) g_gcount[i] = 0;
}

__global__ void k_count_deg(const int* __restrict__ ei) {
    int e = blockIdx.x * blockDim.x + threadIdx.x;
    if (e < NE) atomicAdd(&g_counts[ei[NE + e]], 1);
}

__global__ void __launch_bounds__(1024) k_scan_local() {
    __shared__ int sd[1024];
    int t = threadIdx.x;
    int i = blockIdx.x * 1024 + t;
    int v = 0;
    if (i < NN) {
        v = g_counts[i];
        g_dis[i] = rsqrtf((float)v);
    }
    sd[t] = v;
    __syncthreads();
    #pragma unroll
    for (int off = 1; off < 1024; off <<= 1) {
        int tmp = (t >= off) ? sd[t - off] : 0;
        __syncthreads();
        if (t >= off) sd[t] += tmp;
        __syncthreads();
    }
    if (i < NN) g_offsets[i + 1] = sd[t];
    if (t == 1023) g_part[blockIdx.x] = sd[t];
}

__global__ void k_scan_part() {
    if (threadIdx.x == 0) {
        int running = 0;
        #pragma unroll
        for (int b = 0; b < SCB; b++) {
            int v = g_part[b];
            g_part[b] = running;
            running += v;
        }
        g_offsets[0] = 0;
    }
}

__global__ void __launch_bounds__(1024) k_scan_add() {
    int i = blockIdx.x * 1024 + threadIdx.x;
    if (i < NN) g_offsets[i + 1] += g_part[blockIdx.x];
}

__global__ void k_fill_self() {
    int i = blockIdx.x * blockDim.x + threadIdx.x;
    if (i < NN) {
        int pos = g_offsets[i] + atomicAdd(&g_cursor[i], 1);
        float d = g_dis[i];
        g_csr[pos] = make_int2(i, __float_as_int(d * d));
    }
}

__global__ void k_fill_edges(const int* __restrict__ ei) {
    int e = blockIdx.x * blockDim.x + threadIdx.x;
    if (e < NE) {
        int s = ei[e];
        int d = ei[NE + e];
        int pos = g_offsets[d] + atomicAdd(&g_cursor[d], 1);
        g_csr[pos] = make_int2(s, __float_as_int(g_dis[s] * g_dis[d]));
    }
}

__global__ void k_batch_hist(const int* __restrict__ batch) {
    int i = blockIdx.x * blockDim.x + threadIdx.x;
    if (i < NN) atomicAdd(&g_gcount[batch[i]], 1);
}

__global__ void k_scan_graphs() {
    __shared__ int sd[NG];
    int t = threadIdx.x;
    sd[t] = g_gcount[t];
    __syncthreads();
    #pragma unroll
    for (int off = 1; off < NG; off <<= 1) {
        int tmp = (t >= off) ? sd[t - off] : 0;
        __syncthreads();
        if (t >= off) sd[t] += tmp;
        __syncthreads();
    }
    if (t == 0) g_gstart[0] = 0;
    g_gstart[t + 1] = sd[t];
}

// -------------- weight pack: fp32 [K][256] -> half2 [K/2][256] --------------
__global__ void k_pack_w(const float* __restrict__ enc_w,
                         const float* __restrict__ conv_w) {
    int i = blockIdx.x * blockDim.x + threadIdx.x;
    const int NE_ = (FIN / 2) * HD;
    const int NC_ = NL * (HD / 2) * HD;
    if (i < NE_) {
        int p = i / HD, n = i % HD;
        __half2 h = __floats2half2_rn(enc_w[(2 * p) * HD + n],
                                      enc_w[(2 * p + 1) * HD + n]);
        g_wp_enc[i] = *reinterpret_cast<uint32_t*>(&h);
    }
    int j = i - NE_;
    if (j >= 0 && j < NC_) {
        int l = j / ((HD / 2) * HD);
        int r = j % ((HD / 2) * HD);
        int p = r / HD, n = r % HD;
        const float* W = conv_w + (size_t)l * HD * HD;
        __half2 h = __floats2half2_rn(W[(2 * p) * HD + n],
                                      W[(2 * p + 1) * HD + n]);
        g_wp_conv[j] = *reinterpret_cast<uint32_t*>(&h);
    }
}

// ----------------------- fp16 tensor-core GEMM ------------------------------
// C[M,256] = A[M,K] @ W[K,256] (+bias). Tile 128x128x16, 256 thr, 8 warps 4x2.
// HOUT=false: write fp32 C.  HOUT=true: write fp16 Ch.
__device__ __forceinline__ void mma_f16(float* c, const uint32_t* a,
                                        uint32_t b0, uint32_t b1) {
    asm volatile(
        "mma.sync.aligned.m16n8k16.row.col.f32.f16.f16.f32 "
        "{%0,%1,%2,%3}, {%4,%5,%6,%7}, {%8,%9}, {%0,%1,%2,%3};"
        : "+f"(c[0]), "+f"(c[1]), "+f"(c[2]), "+f"(c[3])
        : "r"(a[0]), "r"(a[1]), "r"(a[2]), "r"(a[3]), "r"(b0), "r"(b1));
}

template <bool HOUT>
__global__ void __launch_bounds__(256) k_gemm_f16(
    const float* __restrict__ A, const uint32_t* __restrict__ Wp,
    const float* __restrict__ bias, float* __restrict__ C,
    __half* __restrict__ Ch, int M, int K)
{
    __shared__ uint32_t As[2][8][136];
    __shared__ uint32_t Bs[2][8][136];

    int tid = threadIdx.x;
    int bm = blockIdx.x * 128;
    int bn = blockIdx.y * 128;

    int lane = tid & 31;
    int warp = tid >> 5;
    int tig  = lane & 3;
    int grp  = lane >> 2;
    int wm   = (warp & 3) * 32;
    int wn   = (warp >> 2) * 64;

    int ar  = bm + (tid >> 1);  if (ar >= M) ar = M - 1;
    int akq = (tid & 1) * 8;
    int ap2 = akq >> 1;
    int bk  = tid >> 5;
    int bc  = (tid & 31) * 4;

    const float*    Apt = A + (size_t)ar * K + akq;
    const uint32_t* Bpt = Wp + (size_t)bk * HD + bn + bc;

    float acc[2][8][4];
    #pragma unroll
    for (int mt = 0; mt < 2; mt++)
        #pragma unroll
        for (int nt = 0; nt < 8; nt++)
            #pragma unroll
            for (int r = 0; r < 4; r++) acc[mt][nt][r] = 0.f;

    int KT = K >> 4;

    float4 rA0 = *(const float4*)(Apt);
    float4 rA1 = *(const float4*)(Apt + 4);
    uint4  rB  = *(const uint4*)(Bpt);

    {
        int arow = tid >> 1;
        __half2 h0 = __floats2half2_rn(rA0.x, rA0.y);
        __half2 h1 = __floats2half2_rn(rA0.z, rA0.w);
        __half2 h2 = __floats2half2_rn(rA1.x, rA1.y);
        __half2 h3 = __floats2half2_rn(rA1.z, rA1.w);
        As[0][ap2 + 0][arow] = *reinterpret_cast<uint32_t*>(&h0);
        As[0][ap2 + 1][arow] = *reinterpret_cast<uint32_t*>(&h1);
        As[0][ap2 + 2][arow] = *reinterpret_cast<uint32_t*>(&h2);
        As[0][ap2 + 3][arow] = *reinterpret_cast<uint32_t*>(&h3);
        Bs[0][bk][bc + 0] = rB.x;
        Bs[0][bk][bc + 1] = rB.y;
        Bs[0][bk][bc + 2] = rB.z;
        Bs[0][bk][bc + 3] = rB.w;
    }
    __syncthreads();

    for (int kt = 0; kt < KT; kt++) {
        int cur = kt & 1;
        int nxt = cur ^ 1;
        if (kt + 1 < KT) {
            const float*    Ap2p = Apt + (kt + 1) * 16;
            const uint32_t* Bp2p = Bpt + (size_t)(kt + 1) * 8 * HD;
            rA0 = *(const float4*)(Ap2p);
            rA1 = *(const float4*)(Ap2p + 4);
            rB  = *(const uint4*)(Bp2p);
        }

        uint32_t a[2][4];
        #pragma unroll
        for (int mt = 0; mt < 2; mt++) {
            int rb = wm + mt * 16 + grp;
            a[mt][0] = As[cur][tig][rb];
            a[mt][1] = As[cur][tig][rb + 8];
            a[mt][2] = As[cur][tig + 4][rb];
            a[mt][3] = As[cur][tig + 4][rb + 8];
        }
        #pragma unroll
        for (int nt = 0; nt < 8; nt++) {
            int nb = wn + nt * 8 + grp;
            uint32_t b0 = Bs[cur][tig][nb];
            uint32_t b1 = Bs[cur][tig + 4][nb];
            mma_f16(acc[0][nt], a[0], b0, b1);
            mma_f16(acc[1][nt], a[1], b0, b1);
        }

        if (kt + 1 < KT) {
            int arow = tid >> 1;
            __half2 h0 = __floats2half2_rn(rA0.x, rA0.y);
            __half2 h1 = __floats2half2_rn(rA0.z, rA0.w);
            __half2 h2 = __floats2half2_rn(rA1.x, rA1.y);
            __half2 h3 = __floats2half2_rn(rA1.z, rA1.w);
            As[nxt][ap2 + 0][arow] = *reinterpret_cast<uint32_t*>(&h0);
            As[nxt][ap2 + 1][arow] = *reinterpret_cast<uint32_t*>(&h1);
            As[nxt][ap2 + 2][arow] = *reinterpret_cast<uint32_t*>(&h2);
            As[nxt][ap2 + 3][arow] = *reinterpret_cast<uint32_t*>(&h3);
            Bs[nxt][bk][bc + 0] = rB.x;
            Bs[nxt][bk][bc + 1] = rB.y;
            Bs[nxt][bk][bc + 2] = rB.z;
            Bs[nxt][bk][bc + 3] = rB.w;
        }
        __syncthreads();
    }

    // epilogue
    #pragma unroll
    for (int mt = 0; mt < 2; mt++) {
        #pragma unroll
        for (int nt = 0; nt < 8; nt++) {
            int col = bn + wn + nt * 8 + tig * 2;
            float b0 = bias ? bias[col]     : 0.f;
            float b1 = bias ? bias[col + 1] : 0.f;
            int r0 = bm + wm + mt * 16 + grp;
            int r1 = r0 + 8;
            if (HOUT) {
                if (r0 < M) {
                    __half2 v = __floats2half2_rn(acc[mt][nt][0] + b0,
                                                  acc[mt][nt][1] + b1);
                    *(__half2*)(Ch + (size_t)r0 * HD + col) = v;
                }
                if (r1 < M) {
                    __half2 v = __floats2half2_rn(acc[mt][nt][2] + b0,
                                                  acc[mt][nt][3] + b1);
                    *(__half2*)(Ch + (size_t)r1 * HD + col) = v;
                }
            } else {
                if (r0 < M) {
                    float2 v = make_float2(acc[mt][nt][0] + b0, acc[mt][nt][1] + b1);
                    *(float2*)(C + (size_t)r0 * HD + col) = v;
                }
                if (r1 < M) {
                    float2 v = make_float2(acc[mt][nt][2] + b0, acc[mt][nt][3] + b1);
                    *(float2*)(C + (size_t)r1 * HD + col) = v;
                }
            }
        }
    }
}

// ----------------------------- CSR aggregation -----------------------------
// 8 nodes/block; 32 threads/node; uint4 = 8 fp16 features/thread; fp32 acc.
__global__ void __launch_bounds__(256) k_aggregate(const float* __restrict__ bias) {
    int grpIdx = threadIdx.x >> 5;           // 0..7
    int t      = threadIdx.x & 31;           // uint4 lane (8 halfs)
    int i = blockIdx.x * 8 + grpIdx;
    if (i >= NN) return;
    int beg = g_offsets[i];
    int end = g_offsets[i + 1];

    float acc[8], acc2[8];
    {
        float4 bA = ((const float4*)bias)[t * 2];
        float4 bB = ((const float4*)bias)[t * 2 + 1];
        acc[0] = bA.x; acc[1] = bA.y; acc[2] = bA.z; acc[3] = bA.w;
        acc[4] = bB.x; acc[5] = bB.y; acc[6] = bB.z; acc[7] = bB.w;
        #pragma unroll
        for (int j = 0; j < 8; j++) acc2[j] = 0.f;
    }

    const uint4* hwv = (const uint4*)g_hwh;   // row stride = 32 uint4
    int e = beg;
    for (; e + 2 <= end; e += 2) {
        int2 p0 = __ldg(&g_csr[e]);
        int2 p1 = __ldg(&g_csr[e + 1]);
        float w0 = __int_as_float(p0.y);
        float w1 = __int_as_float(p1.y);
        uint4 v0 = __ldg(&hwv[(size_t)p0.x * 32 + t]);
        uint4 v1 = __ldg(&hwv[(size_t)p1.x * 32 + t]);
        const __half2* h0 = (const __half2*)&v0;
        const __half2* h1 = (const __half2*)&v1;
        #pragma unroll
        for (int j = 0; j < 4; j++) {
            float2 f0 = __half22float2(h0[j]);
            float2 f1 = __half22float2(h1[j]);
            acc[2*j]   = fmaf(w0, f0.x, acc[2*j]);
            acc[2*j+1] = fmaf(w0, f0.y, acc[2*j+1]);
            acc2[2*j]   = fmaf(w1, f1.x, acc2[2*j]);
            acc2[2*j+1] = fmaf(w1, f1.y, acc2[2*j+1]);
        }
    }
    if (e < end) {
        int2 p = __ldg(&g_csr[e]);
        float w = __int_as_float(p.y);
        uint4 v = __ldg(&hwv[(size_t)p.x * 32 + t]);
        const __half2* hh = (const __half2*)&v;
        #pragma unroll
        for (int j = 0; j < 4; j++) {
            float2 f = __half22float2(hh[j]);
            acc[2*j]   = fmaf(w, f.x, acc[2*j]);
            acc[2*j+1] = fmaf(w, f.y, acc[2*j+1]);
        }
    }
    float4 oA, oB;
    oA.x = acc[0] + acc2[0]; oA.y = acc[1] + acc2[1];
    oA.z = acc[2] + acc2[2]; oA.w = acc[3] + acc2[3];
    oB.x = acc[4] + acc2[4]; oB.y = acc[5] + acc2[5];
    oB.z = acc[6] + acc2[6]; oB.w = acc[7] + acc2[7];
    ((float4*)g_h)[(size_t)i * 64 + t * 2]     = oA;
    ((float4*)g_h)[(size_t)i * 64 + t * 2 + 1] = oB;
}

// -------------------------------- pooling ----------------------------------
__global__ void __launch_bounds__(HD) k_pool() {
    int g = blockIdx.x;
    int f = threadIdx.x;
    int beg = g_gstart[g], end = g_gstart[g + 1];
    float s = 0.f, m = -3.402823e38f;
    for (int i = beg; i < end; ++i) {
        float v = g_h[(size_t)i * HD + f];
        s += v;
        m = fmaxf(m, v);
    }
    int cnt = end - beg;
    g_hg[g * 3 * HD + f]          = s;
    g_hg[g * 3 * HD + HD + f]     = (cnt > 0) ? m : 0.f;
    g_hg[g * 3 * HD + 2 * HD + f] = s / (float)(cnt > 0 ? cnt : 1);
}

// -------------------------------- readout ----------------------------------
__global__ void __launch_bounds__(128) k_readout(
    const float* __restrict__ r1w, const float* __restrict__ r1b,
    const float* __restrict__ r2w, const float* __restrict__ r2b,
    float* __restrict__ out)
{
    int g = blockIdx.x;
    int t = threadIdx.x;
    __shared__ float sh[3 * HD];
    __shared__ float z[128];
    for (int i = t; i < 3 * HD; i += 128) sh[i] = g_hg[g * 3 * HD + i];
    __syncthreads();
    float acc = r1b[t];
    for (int k = 0; k < 3 * HD; k++)
        acc = fmaf(sh[k], r1w[k * 128 + t], acc);
    z[t] = (acc > 0.f) ? acc : 0.01f * acc;
    __syncthreads();
    if (t < NO) {
        float o = r2b[t];
        #pragma unroll 4
        for (int k = 0; k < 128; k++)
            o = fmaf(z[k], r2w[k * NO + t], o);
        out[g * NO + t] = o;
    }
}

// -------------------------------- launcher ---------------------------------
extern "C" void kernel_launch(void* const* d_in, const int* in_sizes, int n_in,
                              void* d_out, int out_size)
{
    const float* x      = (const float*)d_in[0];
    const int*   ei     = (const int*)d_in[1];
    const int*   batch  = (const int*)d_in[2];
    const float* enc_w  = (const float*)d_in[3];
    const float* enc_b  = (const float*)d_in[4];
    const float* conv_w = (const float*)d_in[5];
    const float* conv_b = (const float*)d_in[6];
    const float* r1_w   = (const float*)d_in[7];
    const float* r1_b   = (const float*)d_in[8];
    const float* r2_w   = (const float*)d_in[9];
    const float* r2_b   = (const float*)d_in[10];
    float* out = (float*)d_out;

    float *h;
    __half *hwh;
    uint32_t *wp_enc, *wp_conv;
    cudaGetSymbolAddress((void**)&h,   g_h);
    cudaGetSymbolAddress((void**)&hwh, g_hwh);
    cudaGetSymbolAddress((void**)&wp_enc,  g_wp_enc);
    cudaGetSymbolAddress((void**)&wp_conv, g_wp_conv);

    static cudaStream_t s_side = nullptr;
    static cudaEvent_t  ev_fork = nullptr, ev_join = nullptr;
    if (!s_side) {
        cudaStreamCreateWithFlags(&s_side, cudaStreamNonBlocking);
        cudaEventCreateWithFlags(&ev_fork, cudaEventDisableTiming);
        cudaEventCreateWithFlags(&ev_join, cudaEventDisableTiming);
    }

    const int TB = 256;
    int gN = (NN + TB - 1) / TB;
    int gE = (NE + TB - 1) / TB;
    dim3 grid((NN + 127) / 128, HD / 128);

    // init on origin stream, then fork CSR chain to side stream
    k_init<<<gN, TB>>>();
    cudaEventRecord(ev_fork, 0);
    cudaStreamWaitEvent(s_side, ev_fork, 0);

    // side: CSR build chain
    k_count_deg<<<gE, TB, 0, s_side>>>(ei);
    k_scan_local<<<SCB, 1024, 0, s_side>>>();
    k_scan_part<<<1, 32, 0, s_side>>>();
    k_scan_add<<<SCB, 1024, 0, s_side>>>();
    k_fill_self<<<gN, TB, 0, s_side>>>();
    k_fill_edges<<<gE, TB, 0, s_side>>>(ei);
    cudaEventRecord(ev_join, s_side);

    // origin: weight pack, encoder GEMM, pooling setup (overlapped with side)
    {
        int total = (FIN / 2) * HD + NL * (HD / 2) * HD;
        k_pack_w<<<(total + TB - 1) / TB, TB>>>(enc_w, conv_w);
    }
    k_gemm_f16<false><<<grid, 256>>>(x, wp_enc, enc_b, h, nullptr, NN, FIN);
    k_batch_hist<<<gN, TB>>>(batch);
    k_scan_graphs<<<1, NG>>>();

    // join
    cudaStreamWaitEvent(0, ev_join, 0);

    // conv layers: GEMM writes fp16 hw; aggregate reads fp16, accumulates fp32
    for (int l = 0; l < NL; l++) {
        k_gemm_f16<true><<<grid, 256>>>(h, wp_conv + (size_t)l * (HD / 2) * HD,
                                        nullptr, nullptr, hwh, NN, HD);
        k_aggregate<<<(NN + 7) / 8, 256>>>(conv_b + (size_t)l * HD);
    }

    // pooling + readout
    k_pool<<<NG, HD>>>();
    k_readout<<<NG, 128>>>(r1_w, r1_b, r2_w, r2_b, out);
}

// round 10
// speedup vs baseline: 3.0752x; 1.0518x over previous
#include <cuda_runtime.h>
#include <cuda_fp16.h>
#include <cstdint>

// ---------------------------------------------------------------------------
// GCN forward:  N=50000, E=800000, F_IN=128, H=256, G=256, O=32, L=3
// edge_index / batch are int32.
//
// fp16 carried end-to-end: x->fp16 once; GEMMs (mma.sync m16n8k16, fp32 acc)
// read fp16 A and write fp16; aggregation accumulates fp32, re-emits fp16
// (plus fp32 on the last layer for pooling).
// ---------------------------------------------------------------------------

#define NN 50000
#define NE 800000
#define FIN 128
#define HD 256
#define NG 256
#define NO 32
#define NL 3
#define ETOT (NE + NN)
#define SCB 49

// ----------------------------- device scratch ------------------------------
__device__ float    g_h[(size_t)NN * HD];            // fp32 h (last layer only)
__device__ __half   g_hf16[(size_t)NN * HD];         // fp16 h (GEMM A input)
__device__ __half   g_xh[(size_t)NN * FIN];          // fp16 x
__device__ __half   g_hwh[(size_t)NN * HD];          // fp16 hw (conv GEMM out)
__device__ int      g_counts[NN];
__device__ int      g_cursor[NN];
__device__ float    g_dis[NN];
__device__ int      g_offsets[NN + 1];
__device__ int      g_part[SCB];
__device__ int2     g_csr[ETOT];
__device__ int      g_gcount[NG];
__device__ int      g_gstart[NG + 1];
__device__ float    g_hg[NG * 3 * HD];
__device__ uint32_t g_wp_enc[(FIN / 2) * HD];        // half2(W[2p][n],W[2p+1][n])
__device__ uint32_t g_wp_conv[NL * (HD / 2) * HD];

// ------------------------------ setup kernels ------------------------------
__global__ void k_init() {
    int i = blockIdx.x * blockDim.x + threadIdx.x;
    if (i < NN) { g_counts[i] = 1; g_cursor[i] = 0; }
    if (i < NG) g_gcount[i] = 0;
}

__global__ void k_count_deg(const int* __restrict__ ei) {
    int e = blockIdx.x * blockDim.x + threadIdx.x;
    if (e < NE) atomicAdd(&g_counts[ei[NE + e]], 1);
}

__global__ void __launch_bounds__(1024) k_scan_local() {
    __shared__ int sd[1024];
    int t = threadIdx.x;
    int i = blockIdx.x * 1024 + t;
    int v = 0;
    if (i < NN) {
        v = g_counts[i];
        g_dis[i] = rsqrtf((float)v);
    }
    sd[t] = v;
    __syncthreads();
    #pragma unroll
    for (int off = 1; off < 1024; off <<= 1) {
        int tmp = (t >= off) ? sd[t - off] : 0;
        __syncthreads();
        if (t >= off) sd[t] += tmp;
        __syncthreads();
    }
    if (i < NN) g_offsets[i + 1] = sd[t];
    if (t == 1023) g_part[blockIdx.x] = sd[t];
}

__global__ void k_scan_part() {
    if (threadIdx.x == 0) {
        int running = 0;
        #pragma unroll
        for (int b = 0; b < SCB; b++) {
            int v = g_part[b];
            g_part[b] = running;
            running += v;
        }
        g_offsets[0] = 0;
    }
}

__global__ void __launch_bounds__(1024) k_scan_add() {
    int i = blockIdx.x * 1024 + threadIdx.x;
    if (i < NN) g_offsets[i + 1] += g_part[blockIdx.x];
}

__global__ void k_fill_self() {
    int i = blockIdx.x * blockDim.x + threadIdx.x;
    if (i < NN) {
        int pos = g_offsets[i] + atomicAdd(&g_cursor[i], 1);
        float d = g_dis[i];
        g_csr[pos] = make_int2(i, __float_as_int(d * d));
    }
}

__global__ void k_fill_edges(const int* __restrict__ ei) {
    int e = blockIdx.x * blockDim.x + threadIdx.x;
    if (e < NE) {
        int s = ei[e];
        int d = ei[NE + e];
        int pos = g_offsets[d] + atomicAdd(&g_cursor[d], 1);
        g_csr[pos] = make_int2(s, __float_as_int(g_dis[s] * g_dis[d]));
    }
}

__global__ void k_batch_hist(const int* __restrict__ batch) {
    int i = blockIdx.x * blockDim.x + threadIdx.x;
    if (i < NN) atomicAdd(&g_gcount[batch[i]], 1);
}

__global__ void k_scan_graphs() {
    __shared__ int sd[NG];
    int t = threadIdx.x;
    sd[t] = g_gcount[t];
    __syncthreads();
    #pragma unroll
    for (int off = 1; off < NG; off <<= 1) {
        int tmp = (t >= off) ? sd[t - off] : 0;
        __syncthreads();
        if (t >= off) sd[t] += tmp;
        __syncthreads();
    }
    if (t == 0) g_gstart[0] = 0;
    g_gstart[t + 1] = sd[t];
}

// ------------------- input convert + weight pack (once) ---------------------
__global__ void __launch_bounds__(256) k_conv_x(const float* __restrict__ x) {
    int i = blockIdx.x * blockDim.x + threadIdx.x;      // half2 index
    const int TOT = NN * FIN / 2;
    if (i < TOT) {
        float2 f = ((const float2*)x)[i];
        ((__half2*)g_xh)[i] = __floats2half2_rn(f.x, f.y);
    }
}

__global__ void k_pack_w(const float* __restrict__ enc_w,
                         const float* __restrict__ conv_w) {
    int i = blockIdx.x * blockDim.x + threadIdx.x;
    const int NE_ = (FIN / 2) * HD;
    const int NC_ = NL * (HD / 2) * HD;
    if (i < NE_) {
        int p = i / HD, n = i % HD;
        __half2 h = __floats2half2_rn(enc_w[(2 * p) * HD + n],
                                      enc_w[(2 * p + 1) * HD + n]);
        g_wp_enc[i] = *reinterpret_cast<uint32_t*>(&h);
    }
    int j = i - NE_;
    if (j >= 0 && j < NC_) {
        int l = j / ((HD / 2) * HD);
        int r = j % ((HD / 2) * HD);
        int p = r / HD, n = r % HD;
        const float* W = conv_w + (size_t)l * HD * HD;
        __half2 h = __floats2half2_rn(W[(2 * p) * HD + n],
                                      W[(2 * p + 1) * HD + n]);
        g_wp_conv[j] = *reinterpret_cast<uint32_t*>(&h);
    }
}

// ----------------------- fp16 tensor-core GEMM ------------------------------
// Ch[M,256] = A[M,K] @ W[K,256] (+bias), A fp16, out fp16. Tile 128x128x16.
__device__ __forceinline__ void mma_f16(float* c, const uint32_t* a,
                                        uint32_t b0, uint32_t b1) {
    asm volatile(
        "mma.sync.aligned.m16n8k16.row.col.f32.f16.f16.f32 "
        "{%0,%1,%2,%3}, {%4,%5,%6,%7}, {%8,%9}, {%0,%1,%2,%3};"
        : "+f"(c[0]), "+f"(c[1]), "+f"(c[2]), "+f"(c[3])
        : "r"(a[0]), "r"(a[1]), "r"(a[2]), "r"(a[3]), "r"(b0), "r"(b1));
}

__global__ void __launch_bounds__(256) k_gemm_f16(
    const __half* __restrict__ A, const uint32_t* __restrict__ Wp,
    const float* __restrict__ bias, __half* __restrict__ Ch,
    int M, int K)
{
    __shared__ uint32_t As[2][8][136];
    __shared__ uint32_t Bs[2][8][136];

    int tid = threadIdx.x;
    int bm = blockIdx.x * 128;
    int bn = blockIdx.y * 128;

    int lane = tid & 31;
    int warp = tid >> 5;
    int tig  = lane & 3;
    int grp  = lane >> 2;
    int wm   = (warp & 3) * 32;
    int wn   = (warp >> 2) * 64;

    int ar  = bm + (tid >> 1);  if (ar >= M) ar = M - 1;
    int akq = (tid & 1) * 8;        // half offset within 16-k tile
    int ap2 = akq >> 1;             // k-pair offset (0 or 4)
    int bk  = tid >> 5;
    int bc  = (tid & 31) * 4;

    const __half*   Apt = A + (size_t)ar * K + akq;
    const uint32_t* Bpt = Wp + (size_t)bk * HD + bn + bc;

    float acc[2][8][4];
    #pragma unroll
    for (int mt = 0; mt < 2; mt++)
        #pragma unroll
        for (int nt = 0; nt < 8; nt++)
            #pragma unroll
            for (int r = 0; r < 4; r++) acc[mt][nt][r] = 0.f;

    int KT = K >> 4;

    uint4 rA = *(const uint4*)(Apt);
    uint4 rB = *(const uint4*)(Bpt);

    {
        int arow = tid >> 1;
        As[0][ap2 + 0][arow] = rA.x;
        As[0][ap2 + 1][arow] = rA.y;
        As[0][ap2 + 2][arow] = rA.z;
        As[0][ap2 + 3][arow] = rA.w;
        Bs[0][bk][bc + 0] = rB.x;
        Bs[0][bk][bc + 1] = rB.y;
        Bs[0][bk][bc + 2] = rB.z;
        Bs[0][bk][bc + 3] = rB.w;
    }
    __syncthreads();

    for (int kt = 0; kt < KT; kt++) {
        int cur = kt & 1;
        int nxt = cur ^ 1;
        if (kt + 1 < KT) {
            rA = *(const uint4*)(Apt + (kt + 1) * 16);
            rB = *(const uint4*)(Bpt + (size_t)(kt + 1) * 8 * HD);
        }

        uint32_t a[2][4];
        #pragma unroll
        for (int mt = 0; mt < 2; mt++) {
            int rb = wm + mt * 16 + grp;
            a[mt][0] = As[cur][tig][rb];
            a[mt][1] = As[cur][tig][rb + 8];
            a[mt][2] = As[cur][tig + 4][rb];
            a[mt][3] = As[cur][tig + 4][rb + 8];
        }
        #pragma unroll
        for (int nt = 0; nt < 8; nt++) {
            int nb = wn + nt * 8 + grp;
            uint32_t b0 = Bs[cur][tig][nb];
            uint32_t b1 = Bs[cur][tig + 4][nb];
            mma_f16(acc[0][nt], a[0], b0, b1);
            mma_f16(acc[1][nt], a[1], b0, b1);
        }

        if (kt + 1 < KT) {
            int arow = tid >> 1;
            As[nxt][ap2 + 0][arow] = rA.x;
            As[nxt][ap2 + 1][arow] = rA.y;
            As[nxt][ap2 + 2][arow] = rA.z;
            As[nxt][ap2 + 3][arow] = rA.w;
            Bs[nxt][bk][bc + 0] = rB.x;
            Bs[nxt][bk][bc + 1] = rB.y;
            Bs[nxt][bk][bc + 2] = rB.z;
            Bs[nxt][bk][bc + 3] = rB.w;
        }
        __syncthreads();
    }

    // epilogue: fp16 out
    #pragma unroll
    for (int mt = 0; mt < 2; mt++) {
        #pragma unroll
        for (int nt = 0; nt < 8; nt++) {
            int col = bn + wn + nt * 8 + tig * 2;
            float b0 = bias ? bias[col]     : 0.f;
            float b1 = bias ? bias[col + 1] : 0.f;
            int r0 = bm + wm + mt * 16 + grp;
            int r1 = r0 + 8;
            if (r0 < M) {
                __half2 v = __floats2half2_rn(acc[mt][nt][0] + b0,
                                              acc[mt][nt][1] + b1);
                *(__half2*)(Ch + (size_t)r0 * HD + col) = v;
            }
            if (r1 < M) {
                __half2 v = __floats2half2_rn(acc[mt][nt][2] + b0,
                                              acc[mt][nt][3] + b1);
                *(__half2*)(Ch + (size_t)r1 * HD + col) = v;
            }
        }
    }
}

// ----------------------------- CSR aggregation -----------------------------
// 8 nodes/block; 32 threads/node; uint4 = 8 fp16 features/thread; fp32 acc.
// Writes fp16 h (GEMM input); LAST also writes fp32 h (for pooling).
template <bool LAST>
__global__ void __launch_bounds__(256) k_aggregate(const float* __restrict__ bias) {
    int grpIdx = threadIdx.x >> 5;
    int t      = threadIdx.x & 31;
    int i = blockIdx.x * 8 + grpIdx;
    if (i >= NN) return;
    int beg = g_offsets[i];
    int end = g_offsets[i + 1];

    float acc[8], acc2[8];
    {
        float4 bA = ((const float4*)bias)[t * 2];
        float4 bB = ((const float4*)bias)[t * 2 + 1];
        acc[0] = bA.x; acc[1] = bA.y; acc[2] = bA.z; acc[3] = bA.w;
        acc[4] = bB.x; acc[5] = bB.y; acc[6] = bB.z; acc[7] = bB.w;
        #pragma unroll
        for (int j = 0; j < 8; j++) acc2[j] = 0.f;
    }

    const uint4* hwv = (const uint4*)g_hwh;
    int e = beg;
    for (; e + 2 <= end; e += 2) {
        int2 p0 = __ldg(&g_csr[e]);
        int2 p1 = __ldg(&g_csr[e + 1]);
        float w0 = __int_as_float(p0.y);
        float w1 = __int_as_float(p1.y);
        uint4 v0 = __ldg(&hwv[(size_t)p0.x * 32 + t]);
        uint4 v1 = __ldg(&hwv[(size_t)p1.x * 32 + t]);
        const __half2* h0 = (const __half2*)&v0;
        const __half2* h1 = (const __half2*)&v1;
        #pragma unroll
        for (int j = 0; j < 4; j++) {
            float2 f0 = __half22float2(h0[j]);
            float2 f1 = __half22float2(h1[j]);
            acc[2*j]   = fmaf(w0, f0.x, acc[2*j]);
            acc[2*j+1] = fmaf(w0, f0.y, acc[2*j+1]);
            acc2[2*j]   = fmaf(w1, f1.x, acc2[2*j]);
            acc2[2*j+1] = fmaf(w1, f1.y, acc2[2*j+1]);
        }
    }
    if (e < end) {
        int2 p = __ldg(&g_csr[e]);
        float w = __int_as_float(p.y);
        uint4 v = __ldg(&hwv[(size_t)p.x * 32 + t]);
        const __half2* hh = (const __half2*)&v;
        #pragma unroll
        for (int j = 0; j < 4; j++) {
            float2 f = __half22float2(hh[j]);
            acc[2*j]   = fmaf(w, f.x, acc[2*j]);
            acc[2*j+1] = fmaf(w, f.y, acc[2*j+1]);
        }
    }
    #pragma unroll
    for (int j = 0; j < 8; j++) acc[j] += acc2[j];

    // fp16 h for next GEMM
    uint4 ho;
    __half2 q0 = __floats2half2_rn(acc[0], acc[1]);
    __half2 q1 = __floats2half2_rn(acc[2], acc[3]);
    __half2 q2 = __floats2half2_rn(acc[4], acc[5]);
    __half2 q3 = __floats2half2_rn(acc[6], acc[7]);
    ho.x = *reinterpret_cast<uint32_t*>(&q0);
    ho.y = *reinterpret_cast<uint32_t*>(&q1);
    ho.z = *reinterpret_cast<uint32_t*>(&q2);
    ho.w = *reinterpret_cast<uint32_t*>(&q3);
    ((uint4*)g_hf16)[(size_t)i * 32 + t] = ho;

    if (LAST) {
        float4 oA, oB;
        oA.x = acc[0]; oA.y = acc[1]; oA.z = acc[2]; oA.w = acc[3];
        oB.x = acc[4]; oB.y = acc[5]; oB.z = acc[6]; oB.w = acc[7];
        ((float4*)g_h)[(size_t)i * 64 + t * 2]     = oA;
        ((float4*)g_h)[(size_t)i * 64 + t * 2 + 1] = oB;
    }
}

// -------------------------------- pooling ----------------------------------
__global__ void __launch_bounds__(HD) k_pool() {
    int g = blockIdx.x;
    int f = threadIdx.x;
    int beg = g_gstart[g], end = g_gstart[g + 1];
    float s = 0.f, m = -3.402823e38f;
    for (int i = beg; i < end; ++i) {
        float v = g_h[(size_t)i * HD + f];
        s += v;
        m = fmaxf(m, v);
    }
    int cnt = end - beg;
    g_hg[g * 3 * HD + f]          = s;
    g_hg[g * 3 * HD + HD + f]     = (cnt > 0) ? m : 0.f;
    g_hg[g * 3 * HD + 2 * HD + f] = s / (float)(cnt > 0 ? cnt : 1);
}

// -------------------------------- readout ----------------------------------
__global__ void __launch_bounds__(128) k_readout(
    const float* __restrict__ r1w, const float* __restrict__ r1b,
    const float* __restrict__ r2w, const float* __restrict__ r2b,
    float* __restrict__ out)
{
    int g = blockIdx.x;
    int t = threadIdx.x;
    __shared__ float sh[3 * HD];
    __shared__ float z[128];
    for (int i = t; i < 3 * HD; i += 128) sh[i] = g_hg[g * 3 * HD + i];
    __syncthreads();
    float acc = r1b[t];
    for (int k = 0; k < 3 * HD; k++)
        acc = fmaf(sh[k], r1w[k * 128 + t], acc);
    z[t] = (acc > 0.f) ? acc : 0.01f * acc;
    __syncthreads();
    if (t < NO) {
        float o = r2b[t];
        #pragma unroll 4
        for (int k = 0; k < 128; k++)
            o = fmaf(z[k], r2w[k * NO + t], o);
        out[g * NO + t] = o;
    }
}

// -------------------------------- launcher ---------------------------------
extern "C" void kernel_launch(void* const* d_in, const int* in_sizes, int n_in,
                              void* d_out, int out_size)
{
    const float* x      = (const float*)d_in[0];
    const int*   ei     = (const int*)d_in[1];
    const int*   batch  = (const int*)d_in[2];
    const float* enc_w  = (const float*)d_in[3];
    const float* enc_b  = (const float*)d_in[4];
    const float* conv_w = (const float*)d_in[5];
    const float* conv_b = (const float*)d_in[6];
    const float* r1_w   = (const float*)d_in[7];
    const float* r1_b   = (const float*)d_in[8];
    const float* r2_w   = (const float*)d_in[9];
    const float* r2_b   = (const float*)d_in[10];
    float* out = (float*)d_out;

    __half *hf16, *xh, *hwh;
    uint32_t *wp_enc, *wp_conv;
    cudaGetSymbolAddress((void**)&hf16, g_hf16);
    cudaGetSymbolAddress((void**)&xh,   g_xh);
    cudaGetSymbolAddress((void**)&hwh,  g_hwh);
    cudaGetSymbolAddress((void**)&wp_enc,  g_wp_enc);
    cudaGetSymbolAddress((void**)&wp_conv, g_wp_conv);

    static cudaStream_t s_side = nullptr;
    static cudaEvent_t  ev_fork = nullptr, ev_join = nullptr;
    if (!s_side) {
        cudaStreamCreateWithFlags(&s_side, cudaStreamNonBlocking);
        cudaEventCreateWithFlags(&ev_fork, cudaEventDisableTiming);
        cudaEventCreateWithFlags(&ev_join, cudaEventDisableTiming);
    }

    const int TB = 256;
    int gN = (NN + TB - 1) / TB;
    int gE = (NE + TB - 1) / TB;
    dim3 grid((NN + 127) / 128, HD / 128);

    // init on origin stream, then fork CSR chain to side stream
    k_init<<<gN, TB>>>();
    cudaEventRecord(ev_fork, 0);
    cudaStreamWaitEvent(s_side, ev_fork, 0);

    // side: CSR build chain
    k_count_deg<<<gE, TB, 0, s_side>>>(ei);
    k_scan_local<<<SCB, 1024, 0, s_side>>>();
    k_scan_part<<<1, 32, 0, s_side>>>();
    k_scan_add<<<SCB, 1024, 0, s_side>>>();
    k_fill_self<<<gN, TB, 0, s_side>>>();
    k_fill_edges<<<gE, TB, 0, s_side>>>(ei);
    cudaEventRecord(ev_join, s_side);

    // origin: x convert, weight pack, encoder GEMM, pooling setup (overlapped)
    k_conv_x<<<(NN * FIN / 2 + TB - 1) / TB, TB>>>(x);
    {
        int total = (FIN / 2) * HD + NL * (HD / 2) * HD;
        k_pack_w<<<(total + TB - 1) / TB, TB>>>(enc_w, conv_w);
    }
    k_gemm_f16<<<grid, 256>>>(xh, wp_enc, enc_b, hf16, NN, FIN);
    k_batch_hist<<<gN, TB>>>(batch);
    k_scan_graphs<<<1, NG>>>();

    // join
    cudaStreamWaitEvent(0, ev_join, 0);

    // conv layers
    for (int l = 0; l < NL - 1; l++) {
        k_gemm_f16<<<grid, 256>>>(hf16, wp_conv + (size_t)l * (HD / 2) * HD,
                                  nullptr, hwh, NN, HD);
        k_aggregate<false><<<(NN + 7) / 8, 256>>>(conv_b + (size_t)l * HD);
    }
    k_gemm_f16<<<grid, 256>>>(hf16, wp_conv + (size_t)(NL - 1) * (HD / 2) * HD,
                              nullptr, hwh, NN, HD);
    k_aggregate<true><<<(NN + 7) / 8, 256>>>(conv_b + (size_t)(NL - 1) * HD);

    // pooling + readout
    k_pool<<<NG, HD>>>();
    k_readout<<<NG, 128>>>(r1_w, r1_b, r2_w, r2_b, out);
}

// round 11
// speedup vs baseline: 3.3344x; 1.0843x over previous
#include <cuda_runtime.h>
#include <cuda_fp16.h>
#include <cstdint>

// ---------------------------------------------------------------------------
// GCN forward:  N=50000, E=800000, F_IN=128, H=256, G=256, O=32, L=3
// edge_index / batch are int32.
//
// fp16 carried end-to-end; pooling reads fp16 h; pool+readout fused;
// graph boundaries via binary search on sorted batch.
// ---------------------------------------------------------------------------

#define NN 50000
#define NE 800000
#define FIN 128
#define HD 256
#define NG 256
#define NO 32
#define NL 3
#define ETOT (NE + NN)
#define SCB 49

// ----------------------------- device scratch ------------------------------
__device__ __half   g_hf16[(size_t)NN * HD];         // fp16 h (GEMM A input)
__device__ __half   g_xh[(size_t)NN * FIN];          // fp16 x
__device__ __half   g_hwh[(size_t)NN * HD];          // fp16 hw (conv GEMM out)
__device__ int      g_counts[NN];
__device__ int      g_cursor[NN];
__device__ float    g_dis[NN];
__device__ int      g_offsets[NN + 1];
__device__ int      g_part[SCB];
__device__ int2     g_csr[ETOT];
__device__ int      g_gstart[NG + 1];
__device__ uint32_t g_wp_enc[(FIN / 2) * HD];        // half2(W[2p][n],W[2p+1][n])
__device__ uint32_t g_wp_conv[NL * (HD / 2) * HD];

// ------------------------------ setup kernels ------------------------------
__global__ void k_init() {
    int i = blockIdx.x * blockDim.x + threadIdx.x;
    if (i < NN) { g_counts[i] = 1; g_cursor[i] = 0; }
}

__global__ void k_count_deg(const int* __restrict__ ei) {
    int e = blockIdx.x * blockDim.x + threadIdx.x;
    if (e < NE) atomicAdd(&g_counts[ei[NE + e]], 1);
}

__global__ void __launch_bounds__(1024) k_scan_local() {
    __shared__ int sd[1024];
    int t = threadIdx.x;
    int i = blockIdx.x * 1024 + t;
    int v = 0;
    if (i < NN) {
        v = g_counts[i];
        g_dis[i] = rsqrtf((float)v);
    }
    sd[t] = v;
    __syncthreads();
    #pragma unroll
    for (int off = 1; off < 1024; off <<= 1) {
        int tmp = (t >= off) ? sd[t - off] : 0;
        __syncthreads();
        if (t >= off) sd[t] += tmp;
        __syncthreads();
    }
    if (i < NN) g_offsets[i + 1] = sd[t];
    if (t == 1023) g_part[blockIdx.x] = sd[t];
}

__global__ void k_scan_part() {
    if (threadIdx.x == 0) {
        int running = 0;
        #pragma unroll
        for (int b = 0; b < SCB; b++) {
            int v = g_part[b];
            g_part[b] = running;
            running += v;
        }
        g_offsets[0] = 0;
    }
}

__global__ void __launch_bounds__(1024) k_scan_add() {
    int i = blockIdx.x * 1024 + threadIdx.x;
    if (i < NN) g_offsets[i + 1] += g_part[blockIdx.x];
}

// merged self-loop + edge CSR fill
__global__ void k_fill(const int* __restrict__ ei) {
    int idx = blockIdx.x * blockDim.x + threadIdx.x;
    if (idx < NN) {
        int pos = g_offsets[idx] + atomicAdd(&g_cursor[idx], 1);
        float d = g_dis[idx];
        g_csr[pos] = make_int2(idx, __float_as_int(d * d));
    } else if (idx < NN + NE) {
        int e = idx - NN;
        int s = ei[e];
        int d = ei[NE + e];
        int pos = g_offsets[d] + atomicAdd(&g_cursor[d], 1);
        g_csr[pos] = make_int2(s, __float_as_int(g_dis[s] * g_dis[d]));
    }
}

// graph boundaries: gstart[g] = lower_bound(batch, g)  (batch sorted)
__global__ void k_gsearch(const int* __restrict__ batch) {
    int g = blockIdx.x * blockDim.x + threadIdx.x;
    if (g > NG) return;
    int lo = 0, hi = NN;
    while (lo < hi) {
        int mid = (lo + hi) >> 1;
        if (batch[mid] < g) lo = mid + 1; else hi = mid;
    }
    g_gstart[g] = lo;
}

// ---------------- input convert + weight pack (merged, once) ----------------
__global__ void __launch_bounds__(256) k_prep(const float* __restrict__ x,
                                              const float* __restrict__ enc_w,
                                              const float* __restrict__ conv_w) {
    int i = blockIdx.x * blockDim.x + threadIdx.x;
    const int XT  = NN * FIN / 2;                    // 3.2M half2
    const int NE_ = (FIN / 2) * HD;
    const int NC_ = NL * (HD / 2) * HD;
    if (i < XT) {
        float2 f = ((const float2*)x)[i];
        ((__half2*)g_xh)[i] = __floats2half2_rn(f.x, f.y);
        return;
    }
    int j = i - XT;
    if (j < NE_) {
        int p = j / HD, n = j % HD;
        __half2 h = __floats2half2_rn(enc_w[(2 * p) * HD + n],
                                      enc_w[(2 * p + 1) * HD + n]);
        g_wp_enc[j] = *reinterpret_cast<uint32_t*>(&h);
        return;
    }
    int r0 = j - NE_;
    if (r0 < NC_) {
        int l = r0 / ((HD / 2) * HD);
        int r = r0 % ((HD / 2) * HD);
        int p = r / HD, n = r % HD;
        const float* W = conv_w + (size_t)l * HD * HD;
        __half2 h = __floats2half2_rn(W[(2 * p) * HD + n],
                                      W[(2 * p + 1) * HD + n]);
        g_wp_conv[r0] = *reinterpret_cast<uint32_t*>(&h);
    }
}

// ----------------------- fp16 tensor-core GEMM ------------------------------
__device__ __forceinline__ void mma_f16(float* c, const uint32_t* a,
                                        uint32_t b0, uint32_t b1) {
    asm volatile(
        "mma.sync.aligned.m16n8k16.row.col.f32.f16.f16.f32 "
        "{%0,%1,%2,%3}, {%4,%5,%6,%7}, {%8,%9}, {%0,%1,%2,%3};"
        : "+f"(c[0]), "+f"(c[1]), "+f"(c[2]), "+f"(c[3])
        : "r"(a[0]), "r"(a[1]), "r"(a[2]), "r"(a[3]), "r"(b0), "r"(b1));
}

__global__ void __launch_bounds__(256) k_gemm_f16(
    const __half* __restrict__ A, const uint32_t* __restrict__ Wp,
    const float* __restrict__ bias, __half* __restrict__ Ch,
    int M, int K)
{
    __shared__ uint32_t As[2][8][136];
    __shared__ uint32_t Bs[2][8][136];

    int tid = threadIdx.x;
    int bm = blockIdx.x * 128;
    int bn = blockIdx.y * 128;

    int lane = tid & 31;
    int warp = tid >> 5;
    int tig  = lane & 3;
    int grp  = lane >> 2;
    int wm   = (warp & 3) * 32;
    int wn   = (warp >> 2) * 64;

    int ar  = bm + (tid >> 1);  if (ar >= M) ar = M - 1;
    int akq = (tid & 1) * 8;
    int ap2 = akq >> 1;
    int bk  = tid >> 5;
    int bc  = (tid & 31) * 4;

    const __half*   Apt = A + (size_t)ar * K + akq;
    const uint32_t* Bpt = Wp + (size_t)bk * HD + bn + bc;

    float acc[2][8][4];
    #pragma unroll
    for (int mt = 0; mt < 2; mt++)
        #pragma unroll
        for (int nt = 0; nt < 8; nt++)
            #pragma unroll
            for (int r = 0; r < 4; r++) acc[mt][nt][r] = 0.f;

    int KT = K >> 4;

    uint4 rA = *(const uint4*)(Apt);
    uint4 rB = *(const uint4*)(Bpt);

    {
        int arow = tid >> 1;
        As[0][ap2 + 0][arow] = rA.x;
        As[0][ap2 + 1][arow] = rA.y;
        As[0][ap2 + 2][arow] = rA.z;
        As[0][ap2 + 3][arow] = rA.w;
        Bs[0][bk][bc + 0] = rB.x;
        Bs[0][bk][bc + 1] = rB.y;
        Bs[0][bk][bc + 2] = rB.z;
        Bs[0][bk][bc + 3] = rB.w;
    }
    __syncthreads();

    for (int kt = 0; kt < KT; kt++) {
        int cur = kt & 1;
        int nxt = cur ^ 1;
        if (kt + 1 < KT) {
            rA = *(const uint4*)(Apt + (kt + 1) * 16);
            rB = *(const uint4*)(Bpt + (size_t)(kt + 1) * 8 * HD);
        }

        uint32_t a[2][4];
        #pragma unroll
        for (int mt = 0; mt < 2; mt++) {
            int rb = wm + mt * 16 + grp;
            a[mt][0] = As[cur][tig][rb];
            a[mt][1] = As[cur][tig][rb + 8];
            a[mt][2] = As[cur][tig + 4][rb];
            a[mt][3] = As[cur][tig + 4][rb + 8];
        }
        #pragma unroll
        for (int nt = 0; nt < 8; nt++) {
            int nb = wn + nt * 8 + grp;
            uint32_t b0 = Bs[cur][tig][nb];
            uint32_t b1 = Bs[cur][tig + 4][nb];
            mma_f16(acc[0][nt], a[0], b0, b1);
            mma_f16(acc[1][nt], a[1], b0, b1);
        }

        if (kt + 1 < KT) {
            int arow = tid >> 1;
            As[nxt][ap2 + 0][arow] = rA.x;
            As[nxt][ap2 + 1][arow] = rA.y;
            As[nxt][ap2 + 2][arow] = rA.z;
            As[nxt][ap2 + 3][arow] = rA.w;
            Bs[nxt][bk][bc + 0] = rB.x;
            Bs[nxt][bk][bc + 1] = rB.y;
            Bs[nxt][bk][bc + 2] = rB.z;
            Bs[nxt][bk][bc + 3] = rB.w;
        }
        __syncthreads();
    }

    #pragma unroll
    for (int mt = 0; mt < 2; mt++) {
        #pragma unroll
        for (int nt = 0; nt < 8; nt++) {
            int col = bn + wn + nt * 8 + tig * 2;
            float b0 = bias ? bias[col]     : 0.f;
            float b1 = bias ? bias[col + 1] : 0.f;
            int r0 = bm + wm + mt * 16 + grp;
            int r1 = r0 + 8;
            if (r0 < M) {
                __half2 v = __floats2half2_rn(acc[mt][nt][0] + b0,
                                              acc[mt][nt][1] + b1);
                *(__half2*)(Ch + (size_t)r0 * HD + col) = v;
            }
            if (r1 < M) {
                __half2 v = __floats2half2_rn(acc[mt][nt][2] + b0,
                                              acc[mt][nt][3] + b1);
                *(__half2*)(Ch + (size_t)r1 * HD + col) = v;
            }
        }
    }
}

// ----------------------------- CSR aggregation -----------------------------
// 8 nodes/block; 32 threads/node; uint4 = 8 fp16 features/thread; fp32 acc.
__global__ void __launch_bounds__(256) k_aggregate(const float* __restrict__ bias) {
    int grpIdx = threadIdx.x >> 5;
    int t      = threadIdx.x & 31;
    int i = blockIdx.x * 8 + grpIdx;
    if (i >= NN) return;
    int beg = g_offsets[i];
    int end = g_offsets[i + 1];

    float acc[8], acc2[8];
    {
        float4 bA = ((const float4*)bias)[t * 2];
        float4 bB = ((const float4*)bias)[t * 2 + 1];
        acc[0] = bA.x; acc[1] = bA.y; acc[2] = bA.z; acc[3] = bA.w;
        acc[4] = bB.x; acc[5] = bB.y; acc[6] = bB.z; acc[7] = bB.w;
        #pragma unroll
        for (int j = 0; j < 8; j++) acc2[j] = 0.f;
    }

    const uint4* hwv = (const uint4*)g_hwh;
    int e = beg;
    for (; e + 2 <= end; e += 2) {
        int2 p0 = __ldg(&g_csr[e]);
        int2 p1 = __ldg(&g_csr[e + 1]);
        float w0 = __int_as_float(p0.y);
        float w1 = __int_as_float(p1.y);
        uint4 v0 = __ldg(&hwv[(size_t)p0.x * 32 + t]);
        uint4 v1 = __ldg(&hwv[(size_t)p1.x * 32 + t]);
        const __half2* h0 = (const __half2*)&v0;
        const __half2* h1 = (const __half2*)&v1;
        #pragma unroll
        for (int j = 0; j < 4; j++) {
            float2 f0 = __half22float2(h0[j]);
            float2 f1 = __half22float2(h1[j]);
            acc[2*j]   = fmaf(w0, f0.x, acc[2*j]);
            acc[2*j+1] = fmaf(w0, f0.y, acc[2*j+1]);
            acc2[2*j]   = fmaf(w1, f1.x, acc2[2*j]);
            acc2[2*j+1] = fmaf(w1, f1.y, acc2[2*j+1]);
        }
    }
    if (e < end) {
        int2 p = __ldg(&g_csr[e]);
        float w = __int_as_float(p.y);
        uint4 v = __ldg(&hwv[(size_t)p.x * 32 + t]);
        const __half2* hh = (const __half2*)&v;
        #pragma unroll
        for (int j = 0; j < 4; j++) {
            float2 f = __half22float2(hh[j]);
            acc[2*j]   = fmaf(w, f.x, acc[2*j]);
            acc[2*j+1] = fmaf(w, f.y, acc[2*j+1]);
        }
    }
    #pragma unroll
    for (int j = 0; j < 8; j++) acc[j] += acc2[j];

    uint4 ho;
    __half2 q0 = __floats2half2_rn(acc[0], acc[1]);
    __half2 q1 = __floats2half2_rn(acc[2], acc[3]);
    __half2 q2 = __floats2half2_rn(acc[4], acc[5]);
    __half2 q3 = __floats2half2_rn(acc[6], acc[7]);
    ho.x = *reinterpret_cast<uint32_t*>(&q0);
    ho.y = *reinterpret_cast<uint32_t*>(&q1);
    ho.z = *reinterpret_cast<uint32_t*>(&q2);
    ho.w = *reinterpret_cast<uint32_t*>(&q3);
    ((uint4*)g_hf16)[(size_t)i * 32 + t] = ho;
}

// --------------------- fused pooling + readout MLP --------------------------
__global__ void __launch_bounds__(HD) k_pool_readout(
    const float* __restrict__ r1w, const float* __restrict__ r1b,
    const float* __restrict__ r2w, const float* __restrict__ r2b,
    float* __restrict__ out)
{
    int g = blockIdx.x;
    int t = threadIdx.x;                 // 256 threads, one feature each
    int beg = g_gstart[g], end = g_gstart[g + 1];
    float s = 0.f, m = -3.402823e38f;
    const __half* hp = g_hf16 + t;
    for (int i = beg; i < end; ++i) {
        float v = __half2float(hp[(size_t)i * HD]);
        s += v;
        m = fmaxf(m, v);
    }
    int cnt = end - beg;
    __shared__ float sh[3 * HD];
    sh[t]          = s;
    sh[HD + t]     = (cnt > 0) ? m : 0.f;
    sh[2 * HD + t] = s / (float)(cnt > 0 ? cnt : 1);
    __syncthreads();

    __shared__ float z[128];
    if (t < 128) {
        float acc = r1b[t];
        for (int k = 0; k < 3 * HD; k++)
            acc = fmaf(sh[k], r1w[k * 128 + t], acc);
        z[t] = (acc > 0.f) ? acc : 0.01f * acc;   // leaky_relu(0.01)
    }
    __syncthreads();
    if (t < NO) {
        float o = r2b[t];
        #pragma unroll 4
        for (int k = 0; k < 128; k++)
            o = fmaf(z[k], r2w[k * NO + t], o);
        out[g * NO + t] = o;
    }
}

// -------------------------------- launcher ---------------------------------
extern "C" void kernel_launch(void* const* d_in, const int* in_sizes, int n_in,
                              void* d_out, int out_size)
{
    const float* x      = (const float*)d_in[0];
    const int*   ei     = (const int*)d_in[1];
    const int*   batch  = (const int*)d_in[2];
    const float* enc_w  = (const float*)d_in[3];
    const float* enc_b  = (const float*)d_in[4];
    const float* conv_w = (const float*)d_in[5];
    const float* conv_b = (const float*)d_in[6];
    const float* r1_w   = (const float*)d_in[7];
    const float* r1_b   = (const float*)d_in[8];
    const float* r2_w   = (const float*)d_in[9];
    const float* r2_b   = (const float*)d_in[10];
    float* out = (float*)d_out;

    __half *hf16, *xh, *hwh;
    uint32_t *wp_enc, *wp_conv;
    cudaGetSymbolAddress((void**)&hf16, g_hf16);
    cudaGetSymbolAddress((void**)&xh,   g_xh);
    cudaGetSymbolAddress((void**)&hwh,  g_hwh);
    cudaGetSymbolAddress((void**)&wp_enc,  g_wp_enc);
    cudaGetSymbolAddress((void**)&wp_conv, g_wp_conv);

    static cudaStream_t s_side = nullptr;
    static cudaEvent_t  ev_fork = nullptr, ev_join = nullptr;
    if (!s_side) {
        cudaStreamCreateWithFlags(&s_side, cudaStreamNonBlocking);
        cudaEventCreateWithFlags(&ev_fork, cudaEventDisableTiming);
        cudaEventCreateWithFlags(&ev_join, cudaEventDisableTiming);
    }

    const int TB = 256;
    int gN = (NN + TB - 1) / TB;
    int gE = (NE + TB - 1) / TB;
    dim3 grid((NN + 127) / 128, HD / 128);

    // init on origin stream, then fork CSR chain to side stream
    k_init<<<gN, TB>>>();
    cudaEventRecord(ev_fork, 0);
    cudaStreamWaitEvent(s_side, ev_fork, 0);

    // side: CSR build chain
    k_count_deg<<<gE, TB, 0, s_side>>>(ei);
    k_scan_local<<<SCB, 1024, 0, s_side>>>();
    k_scan_part<<<1, 32, 0, s_side>>>();
    k_scan_add<<<SCB, 1024, 0, s_side>>>();
    k_fill<<<(ETOT + TB - 1) / TB, TB, 0, s_side>>>(ei);
    cudaEventRecord(ev_join, s_side);

    // origin: convert+pack, encoder GEMM, graph bounds (overlapped with side)
    {
        int total = NN * FIN / 2 + (FIN / 2) * HD + NL * (HD / 2) * HD;
        k_prep<<<(total + TB - 1) / TB, TB>>>(x, enc_w, conv_w);
    }
    k_gemm_f16<<<grid, 256>>>(xh, wp_enc, enc_b, hf16, NN, FIN);
    k_gsearch<<<1, 512>>>(batch);

    // join
    cudaStreamWaitEvent(0, ev_join, 0);

    // conv layers
    for (int l = 0; l < NL; l++) {
        k_gemm_f16<<<grid, 256>>>(hf16, wp_conv + (size_t)l * (HD / 2) * HD,
                                  nullptr, hwh, NN, HD);
        k_aggregate<<<(NN + 7) / 8, 256>>>(conv_b + (size_t)l * HD);
    }

    // fused pooling + readout
    k_pool_readout<<<NG, HD>>>(r1_w, r1_b, r2_w, r2_b, out);
}